// round 5
// baseline (speedup 1.0000x reference)
#include <cuda_runtime.h>
#include <math.h>
#include <stdint.h>

#define N_USERS 60000
#define N_ITEMS 40000
#define NU      60001
#define NND     100002
#define D       64
#define ND64    (NND * 64)
#define E_GLOBAL 1000000
#define E_BEH    500000
#define E_TOT   (E_GLOBAL + 3 * E_BEH)
#define BATCH    4096

#define SCB 512
#define NCH ((NND + SCB - 1) / SCB)   /* 196 */

/* ---------------- scratch ---------------- */
__device__ float g_h[ND64];           /* global-encoder current h */
__device__ float g_hw[ND64];          /* global-encoder h@W */
__device__ float g_base[ND64];        /* concat emb, then global res */
__device__ float g_hb[3][ND64];       /* per-behavior current h */
__device__ float g_hwb[3][ND64];      /* per-behavior h@W */
__device__ float g_beh[3][ND64];      /* per-behavior res */
__device__ float g_w[3][ND64];        /* combined uw/iw */
__device__ float g_dinv[4 * NND];
__device__ int   g_deg[4 * NND];
__device__ int   g_part[4 * NCH];
__device__ int   g_ptr[4 * (NND + 1)];
__device__ int   g_cnt[4 * NND];
__device__ int   g_csr[E_TOT];
__device__ float g_sc[2];

/* ---------------- helpers ---------------- */
__device__ __forceinline__ float warp_sum(float v) {
#pragma unroll
    for (int o = 16; o; o >>= 1) v += __shfl_xor_sync(0xffffffffu, v, o);
    return v;
}

#define FMA2(d, a, b) asm("fma.rn.f32x2 %0, %1, %2, %0;" : "+l"(d) : "l"(a), "l"(b))
#define PACK2(p, f)   asm("mov.b64 %0, {%1, %1};" : "=l"(p) : "r"(__float_as_uint(f)))

/* ---------------- zero ---------------- */
__global__ void zero_k(float* out) {
    int i = blockIdx.x * blockDim.x + threadIdx.x;
    if (i < 4 * NND) g_deg[i] = 0;
    if (i < 2) g_sc[i] = 0.0f;
    if (i == 0) out[0] = 0.0f;
}

/* ------------- concat + fused sumsq ------------- */
__global__ void concat_k(const float* __restrict__ ue, const float* __restrict__ ie) {
    int t = blockIdx.x * blockDim.x + threadIdx.x;
    float su = 0.0f, si = 0.0f;
    if (t < NND * 16) {
        int node = t >> 4, q = t & 15;
        float4 v;
        if (node < NU) {
            v = ((const float4*)ue)[node * 16 + q];
            su = v.x * v.x + v.y * v.y + v.z * v.z + v.w * v.w;
        } else {
            v = ((const float4*)ie)[(node - NU) * 16 + q];
            si = v.x * v.x + v.y * v.y + v.z * v.z + v.w * v.w;
        }
        ((float4*)g_base)[t] = v;
    }
    su = warp_sum(su);
    si = warp_sum(si);
    __shared__ float smu[8], smi[8];
    int w = threadIdx.x >> 5, l = threadIdx.x & 31;
    if (l == 0) { smu[w] = su; smi[w] = si; }
    __syncthreads();
    if (threadIdx.x == 0) {
        float a = 0.f, b = 0.f;
#pragma unroll
        for (int q = 0; q < 8; q++) { a += smu[q]; b += smi[q]; }
        if (a != 0.f) atomicAdd(&g_sc[0], a);
        if (b != 0.f) atomicAdd(&g_sc[1], b);
    }
}

/* ---------------- degrees for all 4 graphs in one launch ---------------- */
__global__ void degcnt_all_k(const int* __restrict__ aei, const int* __restrict__ bei) {
    int i = blockIdx.x * blockDim.x + threadIdx.x;
    if (i >= E_TOT) return;
    int g, d;
    if (i < E_GLOBAL) {
        g = 0;
        d = aei[E_GLOBAL + i];
    } else {
        int r = i - E_GLOBAL;
        int b = r / E_BEH, o = r - b * E_BEH;
        g = 1 + b;
        d = bei[(b * 2 + 1) * E_BEH + o];
    }
    atomicAdd(&g_deg[g * NND + d], 1);
}

__global__ void dinv_k() {
    int i = blockIdx.x * blockDim.x + threadIdx.x;
    if (i < 4 * NND) {
        int d = g_deg[i];
        g_dinv[i] = (d > 0) ? rsqrtf((float)d) : 0.0f;
    }
}

/* ---------------- CSR build ---------------- */
__global__ __launch_bounds__(SCB) void part_k() {
    __shared__ int sm[SCB];
    int b = blockIdx.x;
    int g = b / NCH, ch = b % NCH;
    int idx = ch * SCB + threadIdx.x;
    int v = (idx < NND) ? g_deg[g * NND + idx] : 0;
    sm[threadIdx.x] = v;
    __syncthreads();
    for (int o = SCB / 2; o; o >>= 1) {
        if (threadIdx.x < o) sm[threadIdx.x] += sm[threadIdx.x + o];
        __syncthreads();
    }
    if (threadIdx.x == 0) g_part[b] = sm[0];
}

__global__ __launch_bounds__(256) void scanpart_k() {
    __shared__ int sm[256];
    for (int g = 0; g < 4; g++) {
        int v = (threadIdx.x < NCH) ? g_part[g * NCH + threadIdx.x] : 0;
        sm[threadIdx.x] = v;
        __syncthreads();
        for (int o = 1; o < 256; o <<= 1) {
            int a = (threadIdx.x >= o) ? sm[threadIdx.x - o] : 0;
            __syncthreads();
            sm[threadIdx.x] += a;
            __syncthreads();
        }
        if (threadIdx.x < NCH) g_part[g * NCH + threadIdx.x] = sm[threadIdx.x] - v;
        if (threadIdx.x == NCH - 1) g_ptr[g * (NND + 1) + NND] = sm[threadIdx.x];
        __syncthreads();
    }
}

__global__ __launch_bounds__(SCB) void scan_k() {
    __shared__ int sm[SCB];
    int b = blockIdx.x;
    int g = b / NCH, ch = b % NCH;
    int idx = ch * SCB + threadIdx.x;
    int v = (idx < NND) ? g_deg[g * NND + idx] : 0;
    sm[threadIdx.x] = v;
    __syncthreads();
    for (int o = 1; o < SCB; o <<= 1) {
        int add = (threadIdx.x >= o) ? sm[threadIdx.x - o] : 0;
        __syncthreads();
        sm[threadIdx.x] += add;
        __syncthreads();
    }
    int excl = sm[threadIdx.x] - v + g_part[b];
    if (idx < NND) {
        g_ptr[g * (NND + 1) + idx] = excl;
        g_cnt[g * NND + idx]       = excl;
    }
}

__global__ void fill_all_k(const int* __restrict__ aei, const int* __restrict__ bei) {
    int i = blockIdx.x * blockDim.x + threadIdx.x;
    if (i >= E_TOT) return;
    int g, s, d, base;
    if (i < E_GLOBAL) {
        g = 0;
        s = aei[i];
        d = aei[E_GLOBAL + i];
        base = 0;
    } else {
        int r = i - E_GLOBAL;
        int b = r / E_BEH, o = r - b * E_BEH;
        g = 1 + b;
        s = bei[(b * 2) * E_BEH + o];
        d = bei[(b * 2 + 1) * E_BEH + o];
        base = E_GLOBAL + b * E_BEH;
    }
    int pos = atomicAdd(&g_cnt[g * NND + d], 1);
    g_csr[base + pos] = s;
}

/* ---------------- GEMM body: HW[rows] = A[rows] @ W, FFMA2 ---------------- */
__device__ __forceinline__ void gemm_body(const float* __restrict__ A,
                                          const float* __restrict__ W,
                                          float* __restrict__ HW, int row0) {
    __shared__ float sA[64 * 65];
    __shared__ float sW[64 * 64];
    int tid = threadIdx.x;

#pragma unroll
    for (int i = tid; i < 1024; i += 128) ((float4*)sW)[i] = ((const float4*)W)[i];
#pragma unroll
    for (int i = tid; i < 1024; i += 128) {
        int r = i >> 4, kq = i & 15;
        int row = row0 + r;
        float4 v = make_float4(0.f, 0.f, 0.f, 0.f);
        if (row < NND) v = ((const float4*)A)[row * 16 + kq];
        int base = r * 65 + kq * 4;
        sA[base + 0] = v.x; sA[base + 1] = v.y;
        sA[base + 2] = v.z; sA[base + 3] = v.w;
    }
    __syncthreads();

    int tx = tid & 7, ty = tid >> 3;
    int c0 = tx * 4, c1 = 32 + tx * 4, r0 = ty * 4;

    unsigned long long acc[4][4] = {};
    const unsigned long long* sW64 = (const unsigned long long*)sW;

#pragma unroll 8
    for (int k = 0; k < 64; k++) {
        unsigned long long w0 = sW64[(k * 64 + c0) >> 1];
        unsigned long long w1 = sW64[(k * 64 + c0 + 2) >> 1];
        unsigned long long w2 = sW64[(k * 64 + c1) >> 1];
        unsigned long long w3 = sW64[(k * 64 + c1 + 2) >> 1];
#pragma unroll
        for (int i = 0; i < 4; i++) {
            float a = sA[(r0 + i) * 65 + k];
            unsigned long long a2;
            PACK2(a2, a);
            FMA2(acc[i][0], a2, w0);
            FMA2(acc[i][1], a2, w1);
            FMA2(acc[i][2], a2, w2);
            FMA2(acc[i][3], a2, w3);
        }
    }

#pragma unroll
    for (int i = 0; i < 4; i++) {
        int row = row0 + r0 + i;
        if (row >= NND) break;
        float2 p0 = *(float2*)&acc[i][0];
        float2 p1 = *(float2*)&acc[i][1];
        float2 p2 = *(float2*)&acc[i][2];
        float2 p3 = *(float2*)&acc[i][3];
        ((float4*)HW)[row * 16 + tx]     = make_float4(p0.x, p0.y, p1.x, p1.y);
        ((float4*)HW)[row * 16 + 8 + tx] = make_float4(p2.x, p2.y, p3.x, p3.y);
    }
}

/* global-encoder GEMM (srcsel: 0=g_base, 1=g_h) */
__global__ __launch_bounds__(128) void gemm_k(const float* __restrict__ W, int srcsel) {
    gemm_body(srcsel ? g_h : g_base, W, g_hw, blockIdx.x * 64);
}

/* batched behavioral GEMM: gridDim.y = 3 behaviors */
__global__ __launch_bounds__(128) void gemm3_k(const float* __restrict__ bW, int l) {
    int b = blockIdx.y;
    const float* A = l ? g_hb[b] : g_base;
    gemm_body(A, bW + (b * 2 + l) * 4096, g_hwb[b], blockIdx.x * 64);
}

/* ------- gather body ------- */
__device__ __forceinline__ void gather_body(
    const float* __restrict__ HW, int csr_base, int g,
    const float* __restrict__ bias, float invL,
    float* __restrict__ res, const float* __restrict__ res_src,
    float* __restrict__ hout, int node, int lane) {

    const int* ptr = g_ptr + g * (NND + 1);
    const int* csr = g_csr + csr_base;
    const float* dv = g_dinv + g * NND;
    int beg = ptr[node], end = ptr[node + 1];

    float2 acc = make_float2(0.f, 0.f);
    int k = beg;
    for (; k + 4 <= end; k += 4) {
        int s0 = csr[k], s1 = csr[k + 1], s2 = csr[k + 2], s3 = csr[k + 3];
        float c0 = dv[s0], c1 = dv[s1], c2 = dv[s2], c3 = dv[s3];
        float2 v0 = ((const float2*)HW)[s0 * 32 + lane];
        float2 v1 = ((const float2*)HW)[s1 * 32 + lane];
        float2 v2 = ((const float2*)HW)[s2 * 32 + lane];
        float2 v3 = ((const float2*)HW)[s3 * 32 + lane];
        acc.x += c0 * v0.x + c1 * v1.x + c2 * v2.x + c3 * v3.x;
        acc.y += c0 * v0.y + c1 * v1.y + c2 * v2.y + c3 * v3.y;
    }
    for (; k < end; k++) {
        int s = csr[k];
        float c = dv[s];
        float2 v = ((const float2*)HW)[s * 32 + lane];
        acc.x += c * v.x;
        acc.y += c * v.y;
    }

    float dd = dv[node];
    float2 bv = ((const float2*)bias)[lane];
    float2 o = make_float2(acc.x * dd + bv.x, acc.y * dd + bv.y);
    float ss  = warp_sum(o.x * o.x + o.y * o.y);
    float inv = 1.0f / fmaxf(sqrtf(ss), 1e-12f);
    float2 h = make_float2(o.x * inv, o.y * inv);
    if (hout) ((float2*)hout)[node * 32 + lane] = h;

    float2 r = ((const float2*)res_src)[node * 32 + lane];
    ((float2*)res)[node * 32 + lane] = make_float2(r.x + h.x * invL, r.y + h.y * invL);
}

/* global-encoder gather */
__global__ void gather_k(const float* __restrict__ bias, float invL, int write_h) {
    int t = blockIdx.x * blockDim.x + threadIdx.x;
    int node = t >> 5, lane = t & 31;
    if (node >= NND) return;
    gather_body(g_hw, 0, 0, bias, invL, g_base, g_base,
                write_h ? g_h : (float*)0, node, lane);
}

/* batched behavioral gather: warps cover 3*NND nodes */
__global__ void gather3_k(const float* __restrict__ bb, int l) {
    int t = blockIdx.x * blockDim.x + threadIdx.x;
    int w = t >> 5, lane = t & 31;
    if (w >= 3 * NND) return;
    int b = w / NND, node = w - b * NND;
    if (l == 0) {
        gather_body(g_hwb[b], E_GLOBAL + b * E_BEH, 1 + b, bb + (b * 2) * 64,
                    1.0f, g_beh[b], g_base, g_hb[b], node, lane);
    } else {
        gather_body(g_hwb[b], E_GLOBAL + b * E_BEH, 1 + b, bb + (b * 2 + 1) * 64,
                    0.5f, g_beh[b], g_beh[b], (float*)0, node, lane);
    }
}

/* ---------------- attention + combine ---------------- */
__global__ void attn_k() {
    int t = blockIdx.x * blockDim.x + threadIdx.x;
    int node = t >> 5, lane = t & 31;
    if (node >= NND) return;
    int off = node * 32 + lane;
    float2 t0 = ((const float2*)g_beh[0])[off];
    float2 t1 = ((const float2*)g_beh[1])[off];
    float2 t2 = ((const float2*)g_beh[2])[off];

    float s00 = warp_sum(t0.x * t0.x + t0.y * t0.y);
    float s01 = warp_sum(t0.x * t1.x + t0.y * t1.y);
    float s02 = warp_sum(t0.x * t2.x + t0.y * t2.y);
    float s11 = warp_sum(t1.x * t1.x + t1.y * t1.y);
    float s12 = warp_sum(t1.x * t2.x + t1.y * t2.y);
    float s22 = warp_sum(t2.x * t2.x + t2.y * t2.y);

    const float sc = 0.125f;
    float s[3][3] = {{s00 * sc, s01 * sc, s02 * sc},
                     {s01 * sc, s11 * sc, s12 * sc},
                     {s02 * sc, s12 * sc, s22 * sc}};

    bool isU = node < NU;
    float gw = isU ? 2.35f : 1.0f;
    float bw = isU ? 0.242f : 0.55f;
    float2 gv = ((const float2*)g_base)[off];

#pragma unroll
    for (int b = 0; b < 3; b++) {
        float m  = fmaxf(s[b][0], fmaxf(s[b][1], s[b][2]));
        float e0 = __expf(s[b][0] - m), e1 = __expf(s[b][1] - m), e2 = __expf(s[b][2] - m);
        float is = 1.0f / (e0 + e1 + e2);
        float a0 = e0 * is, a1 = e1 * is, a2 = e2 * is;
        float2 o = make_float2(a0 * t0.x + a1 * t1.x + a2 * t2.x,
                               a0 * t0.y + a1 * t1.y + a2 * t2.y);
        ((float2*)g_w[b])[off] = make_float2(gw * gv.x + bw * o.x,
                                             gw * gv.y + bw * o.y);
    }
}

/* ---------------- BPR loss ---------------- */
__global__ void loss_k(const int* __restrict__ bd, float* out) {
    int t = blockIdx.x * blockDim.x + threadIdx.x;
    int w = t >> 5, lane = t & 31;
    float partial = 0.0f;
    if (w < BATCH * 9) {
        int k = w / 9, pr = w - k * 9;
        int i = pr / 3, j = pr - i * 3;
        int u   = bd[k * 9 + i * 3 + 0];
        int ip  = bd[k * 9 + i * 3 + 1];
        int in_ = bd[k * 9 + i * 3 + 2];
        float2 uu = ((const float2*)g_w[i])[u * 32 + lane];
        float2 pp = ((const float2*)g_w[j])[(NU + ip) * 32 + lane];
        float2 nn = ((const float2*)g_w[j])[(NU + in_) * 32 + lane];
        float sp = warp_sum(uu.x * pp.x + uu.y * pp.y);
        float sn = warp_sum(uu.x * nn.x + uu.y * nn.y);
        float x  = sp - sn;
        float ls = fminf(x, 0.0f) - log1pf(expf(-fabsf(x)));
        partial = -ls * (1.0f / (float)BATCH);
    }
    __shared__ float sm[8];
    if (lane == 0) sm[threadIdx.x >> 5] = partial;
    __syncthreads();
    if (threadIdx.x == 0) {
        float s = 0.0f;
#pragma unroll
        for (int q = 0; q < 8; q++) s += sm[q];
        atomicAdd(out, s);
    }
}

__global__ void final_k(float* out) {
    out[0] += 0.001f * ((sqrtf(g_sc[0]) + sqrtf(g_sc[1])) / (float)(N_ITEMS + 1));
}

/* ================================ launch ================================ */
extern "C" void kernel_launch(void* const* d_in, const int* in_sizes, int n_in,
                              void* d_out, int out_size) {
    const float* ue  = (const float*)d_in[0];
    const float* ie  = (const float*)d_in[1];
    const float* gW  = (const float*)d_in[2];
    const float* gb  = (const float*)d_in[3];
    const float* bW  = (const float*)d_in[4];
    const float* bb  = (const float*)d_in[5];
    const int*   aei = (const int*)d_in[6];
    const int*   bei = (const int*)d_in[7];
    const int*   bd  = (const int*)d_in[8];
    float* out = (float*)d_out;

    const int T = 256;
    dim3 blk(T);

    zero_k<<<(4 * NND + T - 1) / T, blk>>>(out);
    concat_k<<<(NND * 16 + T - 1) / T, blk>>>(ue, ie);

    degcnt_all_k<<<(E_TOT + T - 1) / T, blk>>>(aei, bei);
    dinv_k<<<(4 * NND + T - 1) / T, blk>>>();

    part_k<<<4 * NCH, SCB>>>();
    scanpart_k<<<1, 256>>>();
    scan_k<<<4 * NCH, SCB>>>();
    fill_all_k<<<(E_TOT + T - 1) / T, blk>>>(aei, bei);

    const int GEMM_BLOCKS = (NND + 63) / 64;
    const int NODE_BLOCKS  = (NND * 32 + T - 1) / T;
    const int NODE3_BLOCKS = (3 * NND * 32 + T - 1) / T;

    /* global encoder: 2 layers */
    gemm_k<<<GEMM_BLOCKS, 128>>>(gW, 0);
    gather_k<<<NODE_BLOCKS, blk>>>(gb, 1.0f, 1);
    gemm_k<<<GEMM_BLOCKS, 128>>>(gW + 4096, 1);
    gather_k<<<NODE_BLOCKS, blk>>>(gb + 64, 0.5f, 0);

    /* behavioral encoders: batched across the 3 behaviors */
    dim3 g3(GEMM_BLOCKS, 3);
    gemm3_k<<<g3, 128>>>(bW, 0);
    gather3_k<<<NODE3_BLOCKS, blk>>>(bb, 0);
    gemm3_k<<<g3, 128>>>(bW, 1);
    gather3_k<<<NODE3_BLOCKS, blk>>>(bb, 1);

    attn_k<<<NODE_BLOCKS, blk>>>();
    loss_k<<<(BATCH * 9 * 32 + T - 1) / T, blk>>>(bd, out);
    final_k<<<1, 1>>>(out);
}

// round 6
// speedup vs baseline: 1.0572x; 1.0572x over previous
#include <cuda_runtime.h>
#include <math.h>
#include <stdint.h>

#define N_USERS 60000
#define N_ITEMS 40000
#define NU      60001
#define NND     100002
#define D       64
#define ND64    (NND * 64)
#define E_GLOBAL 1000000
#define E_BEH    500000
#define E_TOT   (E_GLOBAL + 3 * E_BEH)
#define BATCH    4096

#define SCB 512
#define NCH ((NND + SCB - 1) / SCB)

/* ---------------- scratch ---------------- */
__device__ float g_h[ND64];           /* global-encoder current h */
__device__ float g_hw[ND64];          /* global-encoder h@W (pre-scaled by dinv[src]) */
__device__ float g_base[ND64];        /* concat emb -> global res */
__device__ float g_hb[3][ND64];       /* per-behavior current h */
__device__ float g_hwb[3][ND64];      /* per-behavior h@W (pre-scaled) */
__device__ float g_beh[3][ND64];      /* per-behavior res after layer 0 */
__device__ float g_w[3][ND64];        /* combined uw/iw */
__device__ float g_dinv[4 * NND];
__device__ int   g_deg[4 * NND];
__device__ int   g_part[4 * NCH];
__device__ int   g_ptr[4 * (NND + 1)];
__device__ int   g_cnt[4 * NND];
__device__ int   g_csr[E_TOT];
__device__ float g_sc[2];

/* ---------------- helpers ---------------- */
__device__ __forceinline__ float warp_sum(float v) {
#pragma unroll
    for (int o = 16; o; o >>= 1) v += __shfl_xor_sync(0xffffffffu, v, o);
    return v;
}

#define FMA2(d, a, b) asm("fma.rn.f32x2 %0, %1, %2, %0;" : "+l"(d) : "l"(a), "l"(b))
#define PACK2(p, f)   asm("mov.b64 %0, {%1, %1};" : "=l"(p) : "r"(__float_as_uint(f)))

/* ---------------- zero ---------------- */
__global__ void zero_k(float* out) {
    int i = blockIdx.x * blockDim.x + threadIdx.x;
    if (i < 4 * NND) g_deg[i] = 0;
    if (i < 2) g_sc[i] = 0.0f;
    if (i == 0) out[0] = 0.0f;
}

/* ------------- concat + fused sumsq ------------- */
__global__ void concat_k(const float* __restrict__ ue, const float* __restrict__ ie) {
    int t = blockIdx.x * blockDim.x + threadIdx.x;
    float su = 0.0f, si = 0.0f;
    if (t < NND * 16) {
        int node = t >> 4, q = t & 15;
        float4 v;
        if (node < NU) {
            v = ((const float4*)ue)[node * 16 + q];
            su = v.x * v.x + v.y * v.y + v.z * v.z + v.w * v.w;
        } else {
            v = ((const float4*)ie)[(node - NU) * 16 + q];
            si = v.x * v.x + v.y * v.y + v.z * v.z + v.w * v.w;
        }
        ((float4*)g_base)[t] = v;
    }
    su = warp_sum(su);
    si = warp_sum(si);
    __shared__ float smu[8], smi[8];
    int w = threadIdx.x >> 5, l = threadIdx.x & 31;
    if (l == 0) { smu[w] = su; smi[w] = si; }
    __syncthreads();
    if (threadIdx.x == 0) {
        float a = 0.f, b = 0.f;
#pragma unroll
        for (int q = 0; q < 8; q++) { a += smu[q]; b += smi[q]; }
        if (a != 0.f) atomicAdd(&g_sc[0], a);
        if (b != 0.f) atomicAdd(&g_sc[1], b);
    }
}

/* ---------------- degrees for all 4 graphs in one launch ---------------- */
__global__ void degcnt_all_k(const int* __restrict__ aei, const int* __restrict__ bei) {
    int i = blockIdx.x * blockDim.x + threadIdx.x;
    if (i >= E_TOT) return;
    int g, d;
    if (i < E_GLOBAL) {
        g = 0;
        d = aei[E_GLOBAL + i];
    } else {
        int r = i - E_GLOBAL;
        int b = r / E_BEH, o = r - b * E_BEH;
        g = 1 + b;
        d = bei[(b * 2 + 1) * E_BEH + o];
    }
    atomicAdd(&g_deg[g * NND + d], 1);
}

__global__ void dinv_k() {
    int i = blockIdx.x * blockDim.x + threadIdx.x;
    if (i < 4 * NND) {
        int d = g_deg[i];
        g_dinv[i] = (d > 0) ? rsqrtf((float)d) : 0.0f;
    }
}

/* ---------------- CSR build ---------------- */
__global__ __launch_bounds__(SCB) void part_k() {
    __shared__ int sm[SCB];
    int b = blockIdx.x;
    int g = b / NCH, ch = b % NCH;
    int idx = ch * SCB + threadIdx.x;
    int v = (idx < NND) ? g_deg[g * NND + idx] : 0;
    sm[threadIdx.x] = v;
    __syncthreads();
    for (int o = SCB / 2; o; o >>= 1) {
        if (threadIdx.x < o) sm[threadIdx.x] += sm[threadIdx.x + o];
        __syncthreads();
    }
    if (threadIdx.x == 0) g_part[b] = sm[0];
}

__global__ __launch_bounds__(256) void scanpart_k() {
    __shared__ int sm[256];
    for (int g = 0; g < 4; g++) {
        int v = (threadIdx.x < NCH) ? g_part[g * NCH + threadIdx.x] : 0;
        sm[threadIdx.x] = v;
        __syncthreads();
        for (int o = 1; o < 256; o <<= 1) {
            int a = (threadIdx.x >= o) ? sm[threadIdx.x - o] : 0;
            __syncthreads();
            sm[threadIdx.x] += a;
            __syncthreads();
        }
        if (threadIdx.x < NCH) g_part[g * NCH + threadIdx.x] = sm[threadIdx.x] - v;
        if (threadIdx.x == NCH - 1) g_ptr[g * (NND + 1) + NND] = sm[threadIdx.x];
        __syncthreads();
    }
}

__global__ __launch_bounds__(SCB) void scan_k() {
    __shared__ int sm[SCB];
    int b = blockIdx.x;
    int g = b / NCH, ch = b % NCH;
    int idx = ch * SCB + threadIdx.x;
    int v = (idx < NND) ? g_deg[g * NND + idx] : 0;
    sm[threadIdx.x] = v;
    __syncthreads();
    for (int o = 1; o < SCB; o <<= 1) {
        int add = (threadIdx.x >= o) ? sm[threadIdx.x - o] : 0;
        __syncthreads();
        sm[threadIdx.x] += add;
        __syncthreads();
    }
    int excl = sm[threadIdx.x] - v + g_part[b];
    if (idx < NND) {
        g_ptr[g * (NND + 1) + idx] = excl;
        g_cnt[g * NND + idx]       = excl;
    }
}

__global__ void fill_all_k(const int* __restrict__ aei, const int* __restrict__ bei) {
    int i = blockIdx.x * blockDim.x + threadIdx.x;
    if (i >= E_TOT) return;
    int g, s, d, base;
    if (i < E_GLOBAL) {
        g = 0;
        s = aei[i];
        d = aei[E_GLOBAL + i];
        base = 0;
    } else {
        int r = i - E_GLOBAL;
        int b = r / E_BEH, o = r - b * E_BEH;
        g = 1 + b;
        s = bei[(b * 2) * E_BEH + o];
        d = bei[(b * 2 + 1) * E_BEH + o];
        base = E_GLOBAL + b * E_BEH;
    }
    int pos = atomicAdd(&g_cnt[g * NND + d], 1);
    g_csr[base + pos] = s;
}

/* --------- GEMM body: HW[row] = dinv_g[row] * (A[row] @ W), FFMA2 --------- */
__device__ __forceinline__ void gemm_body(const float* __restrict__ A,
                                          const float* __restrict__ W,
                                          float* __restrict__ HW, int row0,
                                          const float* __restrict__ dv) {
    __shared__ float sA[64 * 65];
    __shared__ float sW[64 * 64];
    int tid = threadIdx.x;

#pragma unroll
    for (int i = tid; i < 1024; i += 128) ((float4*)sW)[i] = ((const float4*)W)[i];
#pragma unroll
    for (int i = tid; i < 1024; i += 128) {
        int r = i >> 4, kq = i & 15;
        int row = row0 + r;
        float4 v = make_float4(0.f, 0.f, 0.f, 0.f);
        if (row < NND) v = ((const float4*)A)[row * 16 + kq];
        int base = r * 65 + kq * 4;
        sA[base + 0] = v.x; sA[base + 1] = v.y;
        sA[base + 2] = v.z; sA[base + 3] = v.w;
    }
    __syncthreads();

    int tx = tid & 7, ty = tid >> 3;
    int c0 = tx * 4, c1 = 32 + tx * 4, r0 = ty * 4;

    unsigned long long acc[4][4] = {};
    const unsigned long long* sW64 = (const unsigned long long*)sW;

#pragma unroll 8
    for (int k = 0; k < 64; k++) {
        unsigned long long w0 = sW64[(k * 64 + c0) >> 1];
        unsigned long long w1 = sW64[(k * 64 + c0 + 2) >> 1];
        unsigned long long w2 = sW64[(k * 64 + c1) >> 1];
        unsigned long long w3 = sW64[(k * 64 + c1 + 2) >> 1];
#pragma unroll
        for (int i = 0; i < 4; i++) {
            float a = sA[(r0 + i) * 65 + k];
            unsigned long long a2;
            PACK2(a2, a);
            FMA2(acc[i][0], a2, w0);
            FMA2(acc[i][1], a2, w1);
            FMA2(acc[i][2], a2, w2);
            FMA2(acc[i][3], a2, w3);
        }
    }

#pragma unroll
    for (int i = 0; i < 4; i++) {
        int row = row0 + r0 + i;
        if (row >= NND) break;
        float s = dv[row];
        float2 p0 = *(float2*)&acc[i][0];
        float2 p1 = *(float2*)&acc[i][1];
        float2 p2 = *(float2*)&acc[i][2];
        float2 p3 = *(float2*)&acc[i][3];
        ((float4*)HW)[row * 16 + tx]     = make_float4(p0.x * s, p0.y * s, p1.x * s, p1.y * s);
        ((float4*)HW)[row * 16 + 8 + tx] = make_float4(p2.x * s, p2.y * s, p3.x * s, p3.y * s);
    }
}

/* global-encoder GEMM (srcsel: 0=g_base, 1=g_h), graph 0 scaling */
__global__ __launch_bounds__(128) void gemm_k(const float* __restrict__ W, int srcsel) {
    gemm_body(srcsel ? g_h : g_base, W, g_hw, blockIdx.x * 64, g_dinv);
}

/* batched behavioral GEMM: gridDim.y = 3 behaviors, graph 1+b scaling */
__global__ __launch_bounds__(128) void gemm3_k(const float* __restrict__ bW, int l) {
    int b = blockIdx.y;
    const float* A = l ? g_hb[b] : g_base;
    gemm_body(A, bW + (b * 2 + l) * 4096, g_hwb[b], blockIdx.x * 64, g_dinv + (1 + b) * NND);
}

/* ------- gather core: returns normalized h for (node,lane) pair ------- */
__device__ __forceinline__ float2 gather_core(
    const float* __restrict__ HW, int csr_base, int g,
    const float* __restrict__ bias, int node, int lane) {

    const int* ptr = g_ptr + g * (NND + 1);
    const int* csr = g_csr + csr_base;
    int beg = ptr[node], end = ptr[node + 1];

    float2 acc = make_float2(0.f, 0.f);
    int k = beg;
    for (; k + 4 <= end; k += 4) {
        int s0 = csr[k], s1 = csr[k + 1], s2 = csr[k + 2], s3 = csr[k + 3];
        float2 v0 = ((const float2*)HW)[s0 * 32 + lane];
        float2 v1 = ((const float2*)HW)[s1 * 32 + lane];
        float2 v2 = ((const float2*)HW)[s2 * 32 + lane];
        float2 v3 = ((const float2*)HW)[s3 * 32 + lane];
        acc.x += v0.x + v1.x + v2.x + v3.x;
        acc.y += v0.y + v1.y + v2.y + v3.y;
    }
    for (; k < end; k++) {
        int s = csr[k];
        float2 v = ((const float2*)HW)[s * 32 + lane];
        acc.x += v.x;
        acc.y += v.y;
    }

    float dd = g_dinv[g * NND + node];
    float2 bv = ((const float2*)bias)[lane];
    float2 o = make_float2(acc.x * dd + bv.x, acc.y * dd + bv.y);
    float ss  = warp_sum(o.x * o.x + o.y * o.y);
    float inv = 1.0f / fmaxf(sqrtf(ss), 1e-12f);
    return make_float2(o.x * inv, o.y * inv);
}

/* global-encoder gather: res(g_base) += h/L, optionally write h */
__global__ void gather_k(const float* __restrict__ bias, float invL, int write_h) {
    int t = blockIdx.x * blockDim.x + threadIdx.x;
    int node = t >> 5, lane = t & 31;
    if (node >= NND) return;
    float2 h = gather_core(g_hw, 0, 0, bias, node, lane);
    if (write_h) ((float2*)g_h)[node * 32 + lane] = h;
    float2 r = ((const float2*)g_base)[node * 32 + lane];
    ((float2*)g_base)[node * 32 + lane] = make_float2(r.x + h.x * invL, r.y + h.y * invL);
}

/* behavioral layer 0 gather (batched over 3 behaviors): h -> g_hb, res -> g_beh */
__global__ void gather3_k(const float* __restrict__ bb) {
    int t = blockIdx.x * blockDim.x + threadIdx.x;
    int w = t >> 5, lane = t & 31;
    if (w >= 3 * NND) return;
    int b = w / NND, node = w - b * NND;
    float2 h = gather_core(g_hwb[b], E_GLOBAL + b * E_BEH, 1 + b,
                           bb + (b * 2) * 64, node, lane);
    ((float2*)g_hb[b])[node * 32 + lane] = h;
    float2 r = ((const float2*)g_base)[node * 32 + lane];
    ((float2*)g_beh[b])[node * 32 + lane] = make_float2(r.x + h.x, r.y + h.y);
}

/* behavioral layer 1 gather FUSED with mutual attention + combine.
   warp per node: gather all 3 behaviors into registers, attn, write g_w. */
__global__ void gather3attn_k(const float* __restrict__ bb) {
    int t = blockIdx.x * blockDim.x + threadIdx.x;
    int node = t >> 5, lane = t & 31;
    if (node >= NND) return;
    int off = node * 32 + lane;

    float2 tok[3];
#pragma unroll
    for (int b = 0; b < 3; b++) {
        float2 h = gather_core(g_hwb[b], E_GLOBAL + b * E_BEH, 1 + b,
                               bb + (b * 2 + 1) * 64, node, lane);
        float2 r = ((const float2*)g_beh[b])[off];
        tok[b] = make_float2(r.x + 0.5f * h.x, r.y + 0.5f * h.y);
    }

    float s00 = warp_sum(tok[0].x * tok[0].x + tok[0].y * tok[0].y);
    float s01 = warp_sum(tok[0].x * tok[1].x + tok[0].y * tok[1].y);
    float s02 = warp_sum(tok[0].x * tok[2].x + tok[0].y * tok[2].y);
    float s11 = warp_sum(tok[1].x * tok[1].x + tok[1].y * tok[1].y);
    float s12 = warp_sum(tok[1].x * tok[2].x + tok[1].y * tok[2].y);
    float s22 = warp_sum(tok[2].x * tok[2].x + tok[2].y * tok[2].y);

    const float sc = 0.125f;
    float s[3][3] = {{s00 * sc, s01 * sc, s02 * sc},
                     {s01 * sc, s11 * sc, s12 * sc},
                     {s02 * sc, s12 * sc, s22 * sc}};

    bool isU = node < NU;
    float gw = isU ? 2.35f : 1.0f;
    float bw = isU ? 0.242f : 0.55f;
    float2 gv = ((const float2*)g_base)[off];

#pragma unroll
    for (int b = 0; b < 3; b++) {
        float m  = fmaxf(s[b][0], fmaxf(s[b][1], s[b][2]));
        float e0 = __expf(s[b][0] - m), e1 = __expf(s[b][1] - m), e2 = __expf(s[b][2] - m);
        float is = 1.0f / (e0 + e1 + e2);
        float a0 = e0 * is, a1 = e1 * is, a2 = e2 * is;
        float2 o = make_float2(a0 * tok[0].x + a1 * tok[1].x + a2 * tok[2].x,
                               a0 * tok[0].y + a1 * tok[1].y + a2 * tok[2].y);
        ((float2*)g_w[b])[off] = make_float2(gw * gv.x + bw * o.x,
                                             gw * gv.y + bw * o.y);
    }
}

/* ---------------- BPR loss ---------------- */
__global__ void loss_k(const int* __restrict__ bd, float* out) {
    int t = blockIdx.x * blockDim.x + threadIdx.x;
    int w = t >> 5, lane = t & 31;
    float partial = 0.0f;
    if (w < BATCH * 9) {
        int k = w / 9, pr = w - k * 9;
        int i = pr / 3, j = pr - i * 3;
        int u   = bd[k * 9 + i * 3 + 0];
        int ip  = bd[k * 9 + i * 3 + 1];
        int in_ = bd[k * 9 + i * 3 + 2];
        float2 uu = ((const float2*)g_w[i])[u * 32 + lane];
        float2 pp = ((const float2*)g_w[j])[(NU + ip) * 32 + lane];
        float2 nn = ((const float2*)g_w[j])[(NU + in_) * 32 + lane];
        float sp = warp_sum(uu.x * pp.x + uu.y * pp.y);
        float sn = warp_sum(uu.x * nn.x + uu.y * nn.y);
        float x  = sp - sn;
        float ls = fminf(x, 0.0f) - log1pf(expf(-fabsf(x)));
        partial = -ls * (1.0f / (float)BATCH);
    }
    __shared__ float sm[8];
    if (lane == 0) sm[threadIdx.x >> 5] = partial;
    __syncthreads();
    if (threadIdx.x == 0) {
        float s = 0.0f;
#pragma unroll
        for (int q = 0; q < 8; q++) s += sm[q];
        atomicAdd(out, s);
    }
}

__global__ void final_k(float* out) {
    out[0] += 0.001f * ((sqrtf(g_sc[0]) + sqrtf(g_sc[1])) / (float)(N_ITEMS + 1));
}

/* ================================ launch ================================ */
extern "C" void kernel_launch(void* const* d_in, const int* in_sizes, int n_in,
                              void* d_out, int out_size) {
    const float* ue  = (const float*)d_in[0];
    const float* ie  = (const float*)d_in[1];
    const float* gW  = (const float*)d_in[2];
    const float* gb  = (const float*)d_in[3];
    const float* bW  = (const float*)d_in[4];
    const float* bb  = (const float*)d_in[5];
    const int*   aei = (const int*)d_in[6];
    const int*   bei = (const int*)d_in[7];
    const int*   bd  = (const int*)d_in[8];
    float* out = (float*)d_out;

    const int T = 256;
    dim3 blk(T);

    zero_k<<<(4 * NND + T - 1) / T, blk>>>(out);
    concat_k<<<(NND * 16 + T - 1) / T, blk>>>(ue, ie);

    degcnt_all_k<<<(E_TOT + T - 1) / T, blk>>>(aei, bei);
    dinv_k<<<(4 * NND + T - 1) / T, blk>>>();

    part_k<<<4 * NCH, SCB>>>();
    scanpart_k<<<1, 256>>>();
    scan_k<<<4 * NCH, SCB>>>();
    fill_all_k<<<(E_TOT + T - 1) / T, blk>>>(aei, bei);

    const int GEMM_BLOCKS  = (NND + 63) / 64;
    const int NODE_BLOCKS  = (NND * 32 + T - 1) / T;
    const int NODE3_BLOCKS = (3 * NND * 32 + T - 1) / T;

    /* global encoder: 2 layers */
    gemm_k<<<GEMM_BLOCKS, 128>>>(gW, 0);
    gather_k<<<NODE_BLOCKS, blk>>>(gb, 1.0f, 1);
    gemm_k<<<GEMM_BLOCKS, 128>>>(gW + 4096, 1);
    gather_k<<<NODE_BLOCKS, blk>>>(gb + 64, 0.5f, 0);

    /* behavioral encoders */
    dim3 g3(GEMM_BLOCKS, 3);
    gemm3_k<<<g3, 128>>>(bW, 0);
    gather3_k<<<NODE3_BLOCKS, blk>>>(bb);
    gemm3_k<<<g3, 128>>>(bW, 1);
    gather3attn_k<<<NODE_BLOCKS, blk>>>(bb);

    loss_k<<<(BATCH * 9 * 32 + T - 1) / T, blk>>>(bd, out);
    final_k<<<1, 1>>>(out);
}

// round 7
// speedup vs baseline: 1.1007x; 1.0412x over previous
#include <cuda_runtime.h>
#include <cuda_fp16.h>
#include <math.h>
#include <stdint.h>

#define N_USERS 60000
#define N_ITEMS 40000
#define NU      60001
#define NND     100002
#define D       64
#define ND64    (NND * 64)
#define E_GLOBAL 1000000
#define E_BEH    500000
#define E_TOT   (E_GLOBAL + 3 * E_BEH)
#define BATCH    4096

#define SCB 512
#define NCH ((NND + SCB - 1) / SCB)

/* ---------------- scratch ---------------- */
__device__ float  g_h[ND64];          /* global-encoder current h (fp32) */
__device__ __half g_hw[ND64];         /* global-encoder dinv*h@W (fp16) */
__device__ float  g_base[ND64];       /* concat emb -> global res (fp32) */
__device__ float  g_hb[3][ND64];      /* per-behavior current h (fp32) */
__device__ __half g_hwb[3][ND64];     /* per-behavior dinv*h@W (fp16) */
__device__ float  g_beh[3][ND64];     /* per-behavior res after layer 0 */
__device__ float  g_w[3][ND64];       /* combined uw/iw */
__device__ float  g_dinv[4 * NND];
__device__ int    g_deg[4 * NND];
__device__ int    g_part[4 * NCH];
__device__ int    g_ptr[4 * (NND + 1)];
__device__ int    g_cnt[4 * NND];
__device__ int    g_csr[E_TOT];
__device__ float  g_sc[2];

/* ---------------- helpers ---------------- */
__device__ __forceinline__ float warp_sum(float v) {
#pragma unroll
    for (int o = 16; o; o >>= 1) v += __shfl_xor_sync(0xffffffffu, v, o);
    return v;
}

#define FMA2(d, a, b) asm("fma.rn.f32x2 %0, %1, %2, %0;" : "+l"(d) : "l"(a), "l"(b))
#define PACK2(p, f)   asm("mov.b64 %0, {%1, %1};" : "=l"(p) : "r"(__float_as_uint(f)))

/* ---------------- zero ---------------- */
__global__ void zero_k(float* out) {
    int i = blockIdx.x * blockDim.x + threadIdx.x;
    if (i < 4 * NND) g_deg[i] = 0;
    if (i < 2) g_sc[i] = 0.0f;
    if (i == 0) out[0] = 0.0f;
}

/* ------------- concat + fused sumsq ------------- */
__global__ void concat_k(const float* __restrict__ ue, const float* __restrict__ ie) {
    int t = blockIdx.x * blockDim.x + threadIdx.x;
    float su = 0.0f, si = 0.0f;
    if (t < NND * 16) {
        int node = t >> 4, q = t & 15;
        float4 v;
        if (node < NU) {
            v = ((const float4*)ue)[node * 16 + q];
            su = v.x * v.x + v.y * v.y + v.z * v.z + v.w * v.w;
        } else {
            v = ((const float4*)ie)[(node - NU) * 16 + q];
            si = v.x * v.x + v.y * v.y + v.z * v.z + v.w * v.w;
        }
        ((float4*)g_base)[t] = v;
    }
    su = warp_sum(su);
    si = warp_sum(si);
    __shared__ float smu[8], smi[8];
    int w = threadIdx.x >> 5, l = threadIdx.x & 31;
    if (l == 0) { smu[w] = su; smi[w] = si; }
    __syncthreads();
    if (threadIdx.x == 0) {
        float a = 0.f, b = 0.f;
#pragma unroll
        for (int q = 0; q < 8; q++) { a += smu[q]; b += smi[q]; }
        if (a != 0.f) atomicAdd(&g_sc[0], a);
        if (b != 0.f) atomicAdd(&g_sc[1], b);
    }
}

/* ---------------- degrees for all 4 graphs ---------------- */
__global__ void degcnt_all_k(const int* __restrict__ aei, const int* __restrict__ bei) {
    int i = blockIdx.x * blockDim.x + threadIdx.x;
    if (i >= E_TOT) return;
    int g, d;
    if (i < E_GLOBAL) {
        g = 0;
        d = aei[E_GLOBAL + i];
    } else {
        int r = i - E_GLOBAL;
        int b = r / E_BEH, o = r - b * E_BEH;
        g = 1 + b;
        d = bei[(b * 2 + 1) * E_BEH + o];
    }
    atomicAdd(&g_deg[g * NND + d], 1);
}

__global__ void dinv_k() {
    int i = blockIdx.x * blockDim.x + threadIdx.x;
    if (i < 4 * NND) {
        int d = g_deg[i];
        g_dinv[i] = (d > 0) ? rsqrtf((float)d) : 0.0f;
    }
}

/* ---------------- CSR build ---------------- */
__global__ __launch_bounds__(SCB) void part_k() {
    __shared__ int sm[SCB];
    int b = blockIdx.x;
    int g = b / NCH, ch = b % NCH;
    int idx = ch * SCB + threadIdx.x;
    int v = (idx < NND) ? g_deg[g * NND + idx] : 0;
    sm[threadIdx.x] = v;
    __syncthreads();
    for (int o = SCB / 2; o; o >>= 1) {
        if (threadIdx.x < o) sm[threadIdx.x] += sm[threadIdx.x + o];
        __syncthreads();
    }
    if (threadIdx.x == 0) g_part[b] = sm[0];
}

__global__ __launch_bounds__(256) void scanpart_k() {
    __shared__ int sm[256];
    for (int g = 0; g < 4; g++) {
        int v = (threadIdx.x < NCH) ? g_part[g * NCH + threadIdx.x] : 0;
        sm[threadIdx.x] = v;
        __syncthreads();
        for (int o = 1; o < 256; o <<= 1) {
            int a = (threadIdx.x >= o) ? sm[threadIdx.x - o] : 0;
            __syncthreads();
            sm[threadIdx.x] += a;
            __syncthreads();
        }
        if (threadIdx.x < NCH) g_part[g * NCH + threadIdx.x] = sm[threadIdx.x] - v;
        if (threadIdx.x == NCH - 1) g_ptr[g * (NND + 1) + NND] = sm[threadIdx.x];
        __syncthreads();
    }
}

__global__ __launch_bounds__(SCB) void scan_k() {
    __shared__ int sm[SCB];
    int b = blockIdx.x;
    int g = b / NCH, ch = b % NCH;
    int idx = ch * SCB + threadIdx.x;
    int v = (idx < NND) ? g_deg[g * NND + idx] : 0;
    sm[threadIdx.x] = v;
    __syncthreads();
    for (int o = 1; o < SCB; o <<= 1) {
        int add = (threadIdx.x >= o) ? sm[threadIdx.x - o] : 0;
        __syncthreads();
        sm[threadIdx.x] += add;
        __syncthreads();
    }
    int excl = sm[threadIdx.x] - v + g_part[b];
    if (idx < NND) {
        g_ptr[g * (NND + 1) + idx] = excl;
        g_cnt[g * NND + idx]       = excl;
    }
}

__global__ void fill_all_k(const int* __restrict__ aei, const int* __restrict__ bei) {
    int i = blockIdx.x * blockDim.x + threadIdx.x;
    if (i >= E_TOT) return;
    int g, s, d, base;
    if (i < E_GLOBAL) {
        g = 0;
        s = aei[i];
        d = aei[E_GLOBAL + i];
        base = 0;
    } else {
        int r = i - E_GLOBAL;
        int b = r / E_BEH, o = r - b * E_BEH;
        g = 1 + b;
        s = bei[(b * 2) * E_BEH + o];
        d = bei[(b * 2 + 1) * E_BEH + o];
        base = E_GLOBAL + b * E_BEH;
    }
    int pos = atomicAdd(&g_cnt[g * NND + d], 1);
    g_csr[base + pos] = s;
}

/* --------- GEMM body: HW[row] = fp16( dinv_g[row] * (A[row] @ W) ) --------- */
__device__ __forceinline__ void gemm_body(const float* __restrict__ A,
                                          const float* __restrict__ W,
                                          __half* __restrict__ HW, int row0,
                                          const float* __restrict__ dv) {
    __shared__ float sA[64 * 65];
    __shared__ float sW[64 * 64];
    int tid = threadIdx.x;

#pragma unroll
    for (int i = tid; i < 1024; i += 128) ((float4*)sW)[i] = ((const float4*)W)[i];
#pragma unroll
    for (int i = tid; i < 1024; i += 128) {
        int r = i >> 4, kq = i & 15;
        int row = row0 + r;
        float4 v = make_float4(0.f, 0.f, 0.f, 0.f);
        if (row < NND) v = ((const float4*)A)[row * 16 + kq];
        int base = r * 65 + kq * 4;
        sA[base + 0] = v.x; sA[base + 1] = v.y;
        sA[base + 2] = v.z; sA[base + 3] = v.w;
    }
    __syncthreads();

    int tx = tid & 7, ty = tid >> 3;
    int c0 = tx * 4, c1 = 32 + tx * 4, r0 = ty * 4;

    unsigned long long acc[4][4] = {};
    const unsigned long long* sW64 = (const unsigned long long*)sW;

#pragma unroll 8
    for (int k = 0; k < 64; k++) {
        unsigned long long w0 = sW64[(k * 64 + c0) >> 1];
        unsigned long long w1 = sW64[(k * 64 + c0 + 2) >> 1];
        unsigned long long w2 = sW64[(k * 64 + c1) >> 1];
        unsigned long long w3 = sW64[(k * 64 + c1 + 2) >> 1];
#pragma unroll
        for (int i = 0; i < 4; i++) {
            float a = sA[(r0 + i) * 65 + k];
            unsigned long long a2;
            PACK2(a2, a);
            FMA2(acc[i][0], a2, w0);
            FMA2(acc[i][1], a2, w1);
            FMA2(acc[i][2], a2, w2);
            FMA2(acc[i][3], a2, w3);
        }
    }

#pragma unroll
    for (int i = 0; i < 4; i++) {
        int row = row0 + r0 + i;
        if (row >= NND) break;
        float s = dv[row];
        float2 p0 = *(float2*)&acc[i][0];
        float2 p1 = *(float2*)&acc[i][1];
        float2 p2 = *(float2*)&acc[i][2];
        float2 p3 = *(float2*)&acc[i][3];
        __half2 h0 = __floats2half2_rn(p0.x * s, p0.y * s);
        __half2 h1 = __floats2half2_rn(p1.x * s, p1.y * s);
        __half2 h2 = __floats2half2_rn(p2.x * s, p2.y * s);
        __half2 h3 = __floats2half2_rn(p3.x * s, p3.y * s);
        uint2 pa, pb;
        pa.x = *(uint32_t*)&h0; pa.y = *(uint32_t*)&h1;
        pb.x = *(uint32_t*)&h2; pb.y = *(uint32_t*)&h3;
        ((uint2*)HW)[row * 16 + tx]     = pa;   /* cols c0..c0+3 */
        ((uint2*)HW)[row * 16 + 8 + tx] = pb;   /* cols c1..c1+3 */
    }
}

/* global-encoder GEMM (srcsel: 0=g_base, 1=g_h), graph 0 scaling */
__global__ __launch_bounds__(128) void gemm_k(const float* __restrict__ W, int srcsel) {
    gemm_body(srcsel ? g_h : g_base, W, g_hw, blockIdx.x * 64, g_dinv);
}

/* batched behavioral GEMM: gridDim.y = 3 behaviors, graph 1+b scaling */
__global__ __launch_bounds__(128) void gemm3_k(const float* __restrict__ bW, int l) {
    int b = blockIdx.y;
    const float* A = l ? g_hb[b] : g_base;
    gemm_body(A, bW + (b * 2 + l) * 4096, g_hwb[b], blockIdx.x * 64,
              g_dinv + (1 + b) * NND);
}

/* ------- gather core: each lane owns cols 2*lane, 2*lane+1 (half2 loads) ------- */
__device__ __forceinline__ float2 gather_core(
    const __half* __restrict__ HW, int csr_base, int g,
    const float* __restrict__ bias, int node, int lane) {

    const int* ptr = g_ptr + g * (NND + 1);
    const int* csr = g_csr + csr_base;
    const uint32_t* HW32 = (const uint32_t*)HW;   /* 32 half2 words per row */
    int beg = ptr[node], end = ptr[node + 1];

    float2 acc = make_float2(0.f, 0.f);
    int k = beg;
    for (; k + 4 <= end; k += 4) {
        int s0 = csr[k], s1 = csr[k + 1], s2 = csr[k + 2], s3 = csr[k + 3];
        uint32_t u0 = HW32[s0 * 32 + lane];
        uint32_t u1 = HW32[s1 * 32 + lane];
        uint32_t u2 = HW32[s2 * 32 + lane];
        uint32_t u3 = HW32[s3 * 32 + lane];
        float2 v0 = __half22float2(*(__half2*)&u0);
        float2 v1 = __half22float2(*(__half2*)&u1);
        float2 v2 = __half22float2(*(__half2*)&u2);
        float2 v3 = __half22float2(*(__half2*)&u3);
        acc.x += v0.x + v1.x + v2.x + v3.x;
        acc.y += v0.y + v1.y + v2.y + v3.y;
    }
    for (; k < end; k++) {
        int s = csr[k];
        uint32_t u = HW32[s * 32 + lane];
        float2 v = __half22float2(*(__half2*)&u);
        acc.x += v.x;
        acc.y += v.y;
    }

    float dd = g_dinv[g * NND + node];
    float2 bv = ((const float2*)bias)[lane];
    float2 o = make_float2(acc.x * dd + bv.x, acc.y * dd + bv.y);
    float ss  = warp_sum(o.x * o.x + o.y * o.y);
    float inv = 1.0f / fmaxf(sqrtf(ss), 1e-12f);
    return make_float2(o.x * inv, o.y * inv);
}

/* global-encoder gather: res(g_base) += h/L, optionally write h */
__global__ void gather_k(const float* __restrict__ bias, float invL, int write_h) {
    int t = blockIdx.x * blockDim.x + threadIdx.x;
    int node = t >> 5, lane = t & 31;
    if (node >= NND) return;
    float2 h = gather_core(g_hw, 0, 0, bias, node, lane);
    if (write_h) ((float2*)g_h)[node * 32 + lane] = h;
    float2 r = ((const float2*)g_base)[node * 32 + lane];
    ((float2*)g_base)[node * 32 + lane] = make_float2(r.x + h.x * invL, r.y + h.y * invL);
}

/* behavioral layer 0 gather (batched over 3 behaviors): h -> g_hb, res -> g_beh */
__global__ void gather3_k(const float* __restrict__ bb) {
    int t = blockIdx.x * blockDim.x + threadIdx.x;
    int w = t >> 5, lane = t & 31;
    if (w >= 3 * NND) return;
    int b = w / NND, node = w - b * NND;
    float2 h = gather_core(g_hwb[b], E_GLOBAL + b * E_BEH, 1 + b,
                           bb + (b * 2) * 64, node, lane);
    ((float2*)g_hb[b])[node * 32 + lane] = h;
    float2 r = ((const float2*)g_base)[node * 32 + lane];
    ((float2*)g_beh[b])[node * 32 + lane] = make_float2(r.x + h.x, r.y + h.y);
}

/* behavioral layer 1 gather FUSED with mutual attention + combine. */
__global__ void gather3attn_k(const float* __restrict__ bb) {
    int t = blockIdx.x * blockDim.x + threadIdx.x;
    int node = t >> 5, lane = t & 31;
    if (node >= NND) return;
    int off = node * 32 + lane;

    float2 tok[3];
#pragma unroll
    for (int b = 0; b < 3; b++) {
        float2 h = gather_core(g_hwb[b], E_GLOBAL + b * E_BEH, 1 + b,
                               bb + (b * 2 + 1) * 64, node, lane);
        float2 r = ((const float2*)g_beh[b])[off];
        tok[b] = make_float2(r.x + 0.5f * h.x, r.y + 0.5f * h.y);
    }

    float s00 = warp_sum(tok[0].x * tok[0].x + tok[0].y * tok[0].y);
    float s01 = warp_sum(tok[0].x * tok[1].x + tok[0].y * tok[1].y);
    float s02 = warp_sum(tok[0].x * tok[2].x + tok[0].y * tok[2].y);
    float s11 = warp_sum(tok[1].x * tok[1].x + tok[1].y * tok[1].y);
    float s12 = warp_sum(tok[1].x * tok[2].x + tok[1].y * tok[2].y);
    float s22 = warp_sum(tok[2].x * tok[2].x + tok[2].y * tok[2].y);

    const float sc = 0.125f;
    float s[3][3] = {{s00 * sc, s01 * sc, s02 * sc},
                     {s01 * sc, s11 * sc, s12 * sc},
                     {s02 * sc, s12 * sc, s22 * sc}};

    bool isU = node < NU;
    float gw = isU ? 2.35f : 1.0f;
    float bw = isU ? 0.242f : 0.55f;
    float2 gv = ((const float2*)g_base)[off];

#pragma unroll
    for (int b = 0; b < 3; b++) {
        float m  = fmaxf(s[b][0], fmaxf(s[b][1], s[b][2]));
        float e0 = __expf(s[b][0] - m), e1 = __expf(s[b][1] - m), e2 = __expf(s[b][2] - m);
        float is = 1.0f / (e0 + e1 + e2);
        float a0 = e0 * is, a1 = e1 * is, a2 = e2 * is;
        float2 o = make_float2(a0 * tok[0].x + a1 * tok[1].x + a2 * tok[2].x,
                               a0 * tok[0].y + a1 * tok[1].y + a2 * tok[2].y);
        ((float2*)g_w[b])[off] = make_float2(gw * gv.x + bw * o.x,
                                             gw * gv.y + bw * o.y);
    }
}

/* ---------------- BPR loss ---------------- */
__global__ void loss_k(const int* __restrict__ bd, float* out) {
    int t = blockIdx.x * blockDim.x + threadIdx.x;
    int w = t >> 5, lane = t & 31;
    float partial = 0.0f;
    if (w < BATCH * 9) {
        int k = w / 9, pr = w - k * 9;
        int i = pr / 3, j = pr - i * 3;
        int u   = bd[k * 9 + i * 3 + 0];
        int ip  = bd[k * 9 + i * 3 + 1];
        int in_ = bd[k * 9 + i * 3 + 2];
        float2 uu = ((const float2*)g_w[i])[u * 32 + lane];
        float2 pp = ((const float2*)g_w[j])[(NU + ip) * 32 + lane];
        float2 nn = ((const float2*)g_w[j])[(NU + in_) * 32 + lane];
        float sp = warp_sum(uu.x * pp.x + uu.y * pp.y);
        float sn = warp_sum(uu.x * nn.x + uu.y * nn.y);
        float x  = sp - sn;
        float ls = fminf(x, 0.0f) - log1pf(expf(-fabsf(x)));
        partial = -ls * (1.0f / (float)BATCH);
    }
    __shared__ float sm[8];
    if (lane == 0) sm[threadIdx.x >> 5] = partial;
    __syncthreads();
    if (threadIdx.x == 0) {
        float s = 0.0f;
#pragma unroll
        for (int q = 0; q < 8; q++) s += sm[q];
        atomicAdd(out, s);
    }
}

__global__ void final_k(float* out) {
    out[0] += 0.001f * ((sqrtf(g_sc[0]) + sqrtf(g_sc[1])) / (float)(N_ITEMS + 1));
}

/* ================================ launch ================================ */
extern "C" void kernel_launch(void* const* d_in, const int* in_sizes, int n_in,
                              void* d_out, int out_size) {
    const float* ue  = (const float*)d_in[0];
    const float* ie  = (const float*)d_in[1];
    const float* gW  = (const float*)d_in[2];
    const float* gb  = (const float*)d_in[3];
    const float* bW  = (const float*)d_in[4];
    const float* bb  = (const float*)d_in[5];
    const int*   aei = (const int*)d_in[6];
    const int*   bei = (const int*)d_in[7];
    const int*   bd  = (const int*)d_in[8];
    float* out = (float*)d_out;

    const int T = 256;
    dim3 blk(T);

    zero_k<<<(4 * NND + T - 1) / T, blk>>>(out);
    concat_k<<<(NND * 16 + T - 1) / T, blk>>>(ue, ie);

    degcnt_all_k<<<(E_TOT + T - 1) / T, blk>>>(aei, bei);
    dinv_k<<<(4 * NND + T - 1) / T, blk>>>();

    part_k<<<4 * NCH, SCB>>>();
    scanpart_k<<<1, 256>>>();
    scan_k<<<4 * NCH, SCB>>>();
    fill_all_k<<<(E_TOT + T - 1) / T, blk>>>(aei, bei);

    const int GEMM_BLOCKS  = (NND + 63) / 64;
    const int NODE_BLOCKS  = (NND * 32 + T - 1) / T;
    const int NODE3_BLOCKS = (3 * NND * 32 + T - 1) / T;

    /* global encoder: 2 layers */
    gemm_k<<<GEMM_BLOCKS, 128>>>(gW, 0);
    gather_k<<<NODE_BLOCKS, blk>>>(gb, 1.0f, 1);
    gemm_k<<<GEMM_BLOCKS, 128>>>(gW + 4096, 1);
    gather_k<<<NODE_BLOCKS, blk>>>(gb + 64, 0.5f, 0);

    /* behavioral encoders */
    dim3 g3(GEMM_BLOCKS, 3);
    gemm3_k<<<g3, 128>>>(bW, 0);
    gather3_k<<<NODE3_BLOCKS, blk>>>(bb);
    gemm3_k<<<g3, 128>>>(bW, 1);
    gather3attn_k<<<NODE_BLOCKS, blk>>>(bb);

    loss_k<<<(BATCH * 9 * 32 + T - 1) / T, blk>>>(bd, out);
    final_k<<<1, 1>>>(out);
}

// round 8
// speedup vs baseline: 1.1218x; 1.0191x over previous
#include <cuda_runtime.h>
#include <cuda_fp16.h>
#include <math.h>
#include <stdint.h>

#define N_USERS 60000
#define N_ITEMS 40000
#define NU      60001
#define NND     100002
#define D       64
#define ND64    (NND * 64)
#define E_GLOBAL 1000000
#define E_BEH    500000
#define E_TOT   (E_GLOBAL + 3 * E_BEH)
#define BATCH    4096

#define SCB 512
#define NCH ((NND + SCB - 1) / SCB)

/* ---------------- scratch ---------------- */
__device__ __align__(16) __half g_hw[ND64];      /* global dinv*h@W (fp16) */
__device__ __align__(16) __half g_hwb[3][ND64];  /* behavioral dinv*h@W (fp16) */
__device__ __align__(16) __half g_b16[ND64];     /* fp16 copy of GEMM input "base" */
__device__ __align__(16) __half g_h16[ND64];     /* fp16 global h (layer-1 GEMM input) */
__device__ __align__(16) __half g_hb16[3][ND64]; /* fp16 behavioral h */
__device__ float  g_base[ND64];                  /* fp32 global res */
__device__ float  g_beh[3][ND64];                /* fp32 behavioral res */
__device__ float  g_w[3][ND64];                  /* combined uw/iw */
__device__ float  g_dinv[4 * NND];
__device__ int    g_deg[4 * NND];
__device__ int    g_part[4 * NCH];
__device__ int    g_ptr[4 * (NND + 1)];
__device__ int    g_cnt[4 * NND];
__device__ int    g_csr[E_TOT];
__device__ float  g_sc[2];

/* ---------------- helpers ---------------- */
__device__ __forceinline__ float warp_sum(float v) {
#pragma unroll
    for (int o = 16; o; o >>= 1) v += __shfl_xor_sync(0xffffffffu, v, o);
    return v;
}

#define FMA2(d, a, b) asm("fma.rn.f32x2 %0, %1, %2, %0;" : "+l"(d) : "l"(a), "l"(b))
#define PACK2(p, f)   asm("mov.b64 %0, {%1, %1};" : "=l"(p) : "r"(__float_as_uint(f)))

__device__ __forceinline__ uint32_t f2h2(float2 v) {
    __half2 h = __floats2half2_rn(v.x, v.y);
    return *(uint32_t*)&h;
}

/* ---------------- zero ---------------- */
__global__ void zero_k(float* out) {
    int i = blockIdx.x * blockDim.x + threadIdx.x;
    if (i < 4 * NND) g_deg[i] = 0;
    if (i < 2) g_sc[i] = 0.0f;
    if (i == 0) out[0] = 0.0f;
}

/* ------------- concat + fused sumsq + fp16 copy ------------- */
__global__ void concat_k(const float* __restrict__ ue, const float* __restrict__ ie) {
    int t = blockIdx.x * blockDim.x + threadIdx.x;
    float su = 0.0f, si = 0.0f;
    if (t < NND * 16) {
        int node = t >> 4, q = t & 15;
        float4 v;
        if (node < NU) {
            v = ((const float4*)ue)[node * 16 + q];
            su = v.x * v.x + v.y * v.y + v.z * v.z + v.w * v.w;
        } else {
            v = ((const float4*)ie)[(node - NU) * 16 + q];
            si = v.x * v.x + v.y * v.y + v.z * v.z + v.w * v.w;
        }
        ((float4*)g_base)[t] = v;
        uint2 p;
        p.x = f2h2(make_float2(v.x, v.y));
        p.y = f2h2(make_float2(v.z, v.w));
        ((uint2*)g_b16)[t] = p;
    }
    su = warp_sum(su);
    si = warp_sum(si);
    __shared__ float smu[8], smi[8];
    int w = threadIdx.x >> 5, l = threadIdx.x & 31;
    if (l == 0) { smu[w] = su; smi[w] = si; }
    __syncthreads();
    if (threadIdx.x == 0) {
        float a = 0.f, b = 0.f;
#pragma unroll
        for (int q = 0; q < 8; q++) { a += smu[q]; b += smi[q]; }
        if (a != 0.f) atomicAdd(&g_sc[0], a);
        if (b != 0.f) atomicAdd(&g_sc[1], b);
    }
}

/* ---------------- degrees for all 4 graphs ---------------- */
__global__ void degcnt_all_k(const int* __restrict__ aei, const int* __restrict__ bei) {
    int i = blockIdx.x * blockDim.x + threadIdx.x;
    if (i >= E_TOT) return;
    int g, d;
    if (i < E_GLOBAL) {
        g = 0;
        d = aei[E_GLOBAL + i];
    } else {
        int r = i - E_GLOBAL;
        int b = r / E_BEH, o = r - b * E_BEH;
        g = 1 + b;
        d = bei[(b * 2 + 1) * E_BEH + o];
    }
    atomicAdd(&g_deg[g * NND + d], 1);
}

__global__ void dinv_k() {
    int i = blockIdx.x * blockDim.x + threadIdx.x;
    if (i < 4 * NND) {
        int d = g_deg[i];
        g_dinv[i] = (d > 0) ? rsqrtf((float)d) : 0.0f;
    }
}

/* ---------------- CSR build ---------------- */
__global__ __launch_bounds__(SCB) void part_k() {
    __shared__ int sm[SCB];
    int b = blockIdx.x;
    int g = b / NCH, ch = b % NCH;
    int idx = ch * SCB + threadIdx.x;
    int v = (idx < NND) ? g_deg[g * NND + idx] : 0;
    sm[threadIdx.x] = v;
    __syncthreads();
    for (int o = SCB / 2; o; o >>= 1) {
        if (threadIdx.x < o) sm[threadIdx.x] += sm[threadIdx.x + o];
        __syncthreads();
    }
    if (threadIdx.x == 0) g_part[b] = sm[0];
}

__global__ __launch_bounds__(256) void scanpart_k() {
    __shared__ int sm[256];
    for (int g = 0; g < 4; g++) {
        int v = (threadIdx.x < NCH) ? g_part[g * NCH + threadIdx.x] : 0;
        sm[threadIdx.x] = v;
        __syncthreads();
        for (int o = 1; o < 256; o <<= 1) {
            int a = (threadIdx.x >= o) ? sm[threadIdx.x - o] : 0;
            __syncthreads();
            sm[threadIdx.x] += a;
            __syncthreads();
        }
        if (threadIdx.x < NCH) g_part[g * NCH + threadIdx.x] = sm[threadIdx.x] - v;
        if (threadIdx.x == NCH - 1) g_ptr[g * (NND + 1) + NND] = sm[threadIdx.x];
        __syncthreads();
    }
}

__global__ __launch_bounds__(SCB) void scan_k() {
    __shared__ int sm[SCB];
    int b = blockIdx.x;
    int g = b / NCH, ch = b % NCH;
    int idx = ch * SCB + threadIdx.x;
    int v = (idx < NND) ? g_deg[g * NND + idx] : 0;
    sm[threadIdx.x] = v;
    __syncthreads();
    for (int o = 1; o < SCB; o <<= 1) {
        int add = (threadIdx.x >= o) ? sm[threadIdx.x - o] : 0;
        __syncthreads();
        sm[threadIdx.x] += add;
        __syncthreads();
    }
    int excl = sm[threadIdx.x] - v + g_part[b];
    if (idx < NND) {
        g_ptr[g * (NND + 1) + idx] = excl;
        g_cnt[g * NND + idx]       = excl;
    }
}

__global__ void fill_all_k(const int* __restrict__ aei, const int* __restrict__ bei) {
    int i = blockIdx.x * blockDim.x + threadIdx.x;
    if (i >= E_TOT) return;
    int g, s, d, base;
    if (i < E_GLOBAL) {
        g = 0;
        s = aei[i];
        d = aei[E_GLOBAL + i];
        base = 0;
    } else {
        int r = i - E_GLOBAL;
        int b = r / E_BEH, o = r - b * E_BEH;
        g = 1 + b;
        s = bei[(b * 2) * E_BEH + o];
        d = bei[(b * 2 + 1) * E_BEH + o];
        base = E_GLOBAL + b * E_BEH;
    }
    int pos = atomicAdd(&g_cnt[g * NND + d], 1);
    g_csr[base + pos] = s;
}

/* --------- GEMM body: HW = fp16(dinv * (A16 @ W)), A16 fp16 input --------- */
__device__ __forceinline__ void gemm_body(const __half* __restrict__ A16,
                                          const float* __restrict__ W,
                                          __half* __restrict__ HW, int row0,
                                          const float* __restrict__ dv) {
    __shared__ float sA[64 * 65];
    __shared__ float sW[64 * 64];
    int tid = threadIdx.x;

#pragma unroll
    for (int i = tid; i < 1024; i += 128) ((float4*)sW)[i] = ((const float4*)W)[i];
#pragma unroll
    for (int i = tid; i < 1024; i += 128) {
        int r = i >> 4, q = i & 15;
        int row = row0 + r;
        uint2 u = make_uint2(0u, 0u);
        if (row < NND) u = ((const uint2*)A16)[row * 16 + q];
        float2 f0 = __half22float2(*(__half2*)&u.x);
        float2 f1 = __half22float2(*(__half2*)&u.y);
        int base = r * 65 + q * 4;
        sA[base + 0] = f0.x; sA[base + 1] = f0.y;
        sA[base + 2] = f1.x; sA[base + 3] = f1.y;
    }
    __syncthreads();

    int tx = tid & 7, ty = tid >> 3;
    int c0 = tx * 4, c1 = 32 + tx * 4, r0 = ty * 4;

    unsigned long long acc[4][4] = {};
    const unsigned long long* sW64 = (const unsigned long long*)sW;

#pragma unroll 8
    for (int k = 0; k < 64; k++) {
        unsigned long long w0 = sW64[(k * 64 + c0) >> 1];
        unsigned long long w1 = sW64[(k * 64 + c0 + 2) >> 1];
        unsigned long long w2 = sW64[(k * 64 + c1) >> 1];
        unsigned long long w3 = sW64[(k * 64 + c1 + 2) >> 1];
#pragma unroll
        for (int i = 0; i < 4; i++) {
            float a = sA[(r0 + i) * 65 + k];
            unsigned long long a2;
            PACK2(a2, a);
            FMA2(acc[i][0], a2, w0);
            FMA2(acc[i][1], a2, w1);
            FMA2(acc[i][2], a2, w2);
            FMA2(acc[i][3], a2, w3);
        }
    }

#pragma unroll
    for (int i = 0; i < 4; i++) {
        int row = row0 + r0 + i;
        if (row >= NND) break;
        float s = dv[row];
        float2 p0 = *(float2*)&acc[i][0];
        float2 p1 = *(float2*)&acc[i][1];
        float2 p2 = *(float2*)&acc[i][2];
        float2 p3 = *(float2*)&acc[i][3];
        uint2 pa, pb;
        pa.x = f2h2(make_float2(p0.x * s, p0.y * s));
        pa.y = f2h2(make_float2(p1.x * s, p1.y * s));
        pb.x = f2h2(make_float2(p2.x * s, p2.y * s));
        pb.y = f2h2(make_float2(p3.x * s, p3.y * s));
        ((uint2*)HW)[row * 16 + tx]     = pa;
        ((uint2*)HW)[row * 16 + 8 + tx] = pb;
    }
}

/* global-encoder GEMM (srcsel: 0=g_b16, 1=g_h16), graph 0 scaling */
__global__ __launch_bounds__(128) void gemm_k(const float* __restrict__ W, int srcsel) {
    gemm_body(srcsel ? g_h16 : g_b16, W, g_hw, blockIdx.x * 64, g_dinv);
}

/* batched behavioral GEMM: gridDim.y = 3 behaviors, graph 1+b scaling */
__global__ __launch_bounds__(128) void gemm3_k(const float* __restrict__ bW, int l) {
    int b = blockIdx.y;
    const __half* A16 = l ? g_hb16[b] : g_b16;
    gemm_body(A16, bW + (b * 2 + l) * 4096, g_hwb[b], blockIdx.x * 64,
              g_dinv + (1 + b) * NND);
}

/* ------- gather core: lane owns cols 2*lane, 2*lane+1; unroll 8 ------- */
__device__ __forceinline__ float2 gather_core(
    const __half* __restrict__ HW, int csr_base, int g,
    const float* __restrict__ bias, int node, int lane) {

    const int* ptr = g_ptr + g * (NND + 1);
    const int* csr = g_csr + csr_base;
    const uint32_t* HW32 = (const uint32_t*)HW;
    int beg = ptr[node], end = ptr[node + 1];

    float2 acc = make_float2(0.f, 0.f);
    int k = beg;
    for (; k + 8 <= end; k += 8) {
        uint32_t u[8];
#pragma unroll
        for (int j = 0; j < 8; j++) u[j] = HW32[csr[k + j] * 32 + lane];
#pragma unroll
        for (int j = 0; j < 8; j++) {
            float2 v = __half22float2(*(__half2*)&u[j]);
            acc.x += v.x;
            acc.y += v.y;
        }
    }
    for (; k + 4 <= end; k += 4) {
        uint32_t u[4];
#pragma unroll
        for (int j = 0; j < 4; j++) u[j] = HW32[csr[k + j] * 32 + lane];
#pragma unroll
        for (int j = 0; j < 4; j++) {
            float2 v = __half22float2(*(__half2*)&u[j]);
            acc.x += v.x;
            acc.y += v.y;
        }
    }
    for (; k < end; k++) {
        uint32_t u = HW32[csr[k] * 32 + lane];
        float2 v = __half22float2(*(__half2*)&u);
        acc.x += v.x;
        acc.y += v.y;
    }

    float dd = g_dinv[g * NND + node];
    float2 bv = ((const float2*)bias)[lane];
    float2 o = make_float2(acc.x * dd + bv.x, acc.y * dd + bv.y);
    float ss  = warp_sum(o.x * o.x + o.y * o.y);
    float inv = 1.0f / fmaxf(sqrtf(ss), 1e-12f);
    return make_float2(o.x * inv, o.y * inv);
}

/* global gather. mode 0 (layer 1): base += h, h16 = h.
   mode 1 (layer 2): base += h/2, b16 = fp16(base). */
__global__ void gather_k(const float* __restrict__ bias, int mode) {
    int t = blockIdx.x * blockDim.x + threadIdx.x;
    int node = t >> 5, lane = t & 31;
    if (node >= NND) return;
    int off = node * 32 + lane;
    float2 h = gather_core(g_hw, 0, 0, bias, node, lane);
    float2 r = ((const float2*)g_base)[off];
    if (mode == 0) {
        float2 nb = make_float2(r.x + h.x, r.y + h.y);
        ((float2*)g_base)[off] = nb;
        ((uint32_t*)g_h16)[off] = f2h2(h);
    } else {
        float2 nb = make_float2(r.x + 0.5f * h.x, r.y + 0.5f * h.y);
        ((float2*)g_base)[off] = nb;
        ((uint32_t*)g_b16)[off] = f2h2(nb);
    }
}

/* behavioral layer 0 gather (batched): h16 -> g_hb16, res -> g_beh */
__global__ void gather3_k(const float* __restrict__ bb) {
    int t = blockIdx.x * blockDim.x + threadIdx.x;
    int w = t >> 5, lane = t & 31;
    if (w >= 3 * NND) return;
    int b = w / NND, node = w - b * NND;
    int off = node * 32 + lane;
    float2 h = gather_core(g_hwb[b], E_GLOBAL + b * E_BEH, 1 + b,
                           bb + (b * 2) * 64, node, lane);
    ((uint32_t*)g_hb16[b])[off] = f2h2(h);
    float2 r = ((const float2*)g_base)[off];
    ((float2*)g_beh[b])[off] = make_float2(r.x + h.x, r.y + h.y);
}

/* behavioral layer 1 gather FUSED with mutual attention + combine. */
__global__ void gather3attn_k(const float* __restrict__ bb) {
    int t = blockIdx.x * blockDim.x + threadIdx.x;
    int node = t >> 5, lane = t & 31;
    if (node >= NND) return;
    int off = node * 32 + lane;

    float2 tok[3];
#pragma unroll
    for (int b = 0; b < 3; b++) {
        float2 h = gather_core(g_hwb[b], E_GLOBAL + b * E_BEH, 1 + b,
                               bb + (b * 2 + 1) * 64, node, lane);
        float2 r = ((const float2*)g_beh[b])[off];
        tok[b] = make_float2(r.x + 0.5f * h.x, r.y + 0.5f * h.y);
    }

    float s00 = warp_sum(tok[0].x * tok[0].x + tok[0].y * tok[0].y);
    float s01 = warp_sum(tok[0].x * tok[1].x + tok[0].y * tok[1].y);
    float s02 = warp_sum(tok[0].x * tok[2].x + tok[0].y * tok[2].y);
    float s11 = warp_sum(tok[1].x * tok[1].x + tok[1].y * tok[1].y);
    float s12 = warp_sum(tok[1].x * tok[2].x + tok[1].y * tok[2].y);
    float s22 = warp_sum(tok[2].x * tok[2].x + tok[2].y * tok[2].y);

    const float sc = 0.125f;
    float s[3][3] = {{s00 * sc, s01 * sc, s02 * sc},
                     {s01 * sc, s11 * sc, s12 * sc},
                     {s02 * sc, s12 * sc, s22 * sc}};

    bool isU = node < NU;
    float gw = isU ? 2.35f : 1.0f;
    float bw = isU ? 0.242f : 0.55f;
    float2 gv = ((const float2*)g_base)[off];

#pragma unroll
    for (int b = 0; b < 3; b++) {
        float m  = fmaxf(s[b][0], fmaxf(s[b][1], s[b][2]));
        float e0 = __expf(s[b][0] - m), e1 = __expf(s[b][1] - m), e2 = __expf(s[b][2] - m);
        float is = 1.0f / (e0 + e1 + e2);
        float a0 = e0 * is, a1 = e1 * is, a2 = e2 * is;
        float2 o = make_float2(a0 * tok[0].x + a1 * tok[1].x + a2 * tok[2].x,
                               a0 * tok[0].y + a1 * tok[1].y + a2 * tok[2].y);
        ((float2*)g_w[b])[off] = make_float2(gw * gv.x + bw * o.x,
                                             gw * gv.y + bw * o.y);
    }
}

/* ---------------- BPR loss ---------------- */
__global__ void loss_k(const int* __restrict__ bd, float* out) {
    int t = blockIdx.x * blockDim.x + threadIdx.x;
    int w = t >> 5, lane = t & 31;
    float partial = 0.0f;
    if (w < BATCH * 9) {
        int k = w / 9, pr = w - k * 9;
        int i = pr / 3, j = pr - i * 3;
        int u   = bd[k * 9 + i * 3 + 0];
        int ip  = bd[k * 9 + i * 3 + 1];
        int in_ = bd[k * 9 + i * 3 + 2];
        float2 uu = ((const float2*)g_w[i])[u * 32 + lane];
        float2 pp = ((const float2*)g_w[j])[(NU + ip) * 32 + lane];
        float2 nn = ((const float2*)g_w[j])[(NU + in_) * 32 + lane];
        float sp = warp_sum(uu.x * pp.x + uu.y * pp.y);
        float sn = warp_sum(uu.x * nn.x + uu.y * nn.y);
        float x  = sp - sn;
        float ls = fminf(x, 0.0f) - log1pf(expf(-fabsf(x)));
        partial = -ls * (1.0f / (float)BATCH);
    }
    __shared__ float sm[8];
    if (lane == 0) sm[threadIdx.x >> 5] = partial;
    __syncthreads();
    if (threadIdx.x == 0) {
        float s = 0.0f;
#pragma unroll
        for (int q = 0; q < 8; q++) s += sm[q];
        atomicAdd(out, s);
    }
}

__global__ void final_k(float* out) {
    out[0] += 0.001f * ((sqrtf(g_sc[0]) + sqrtf(g_sc[1])) / (float)(N_ITEMS + 1));
}

/* ================================ launch ================================ */
extern "C" void kernel_launch(void* const* d_in, const int* in_sizes, int n_in,
                              void* d_out, int out_size) {
    const float* ue  = (const float*)d_in[0];
    const float* ie  = (const float*)d_in[1];
    const float* gW  = (const float*)d_in[2];
    const float* gb  = (const float*)d_in[3];
    const float* bW  = (const float*)d_in[4];
    const float* bb  = (const float*)d_in[5];
    const int*   aei = (const int*)d_in[6];
    const int*   bei = (const int*)d_in[7];
    const int*   bd  = (const int*)d_in[8];
    float* out = (float*)d_out;

    const int T = 256;
    dim3 blk(T);

    zero_k<<<(4 * NND + T - 1) / T, blk>>>(out);
    concat_k<<<(NND * 16 + T - 1) / T, blk>>>(ue, ie);

    degcnt_all_k<<<(E_TOT + T - 1) / T, blk>>>(aei, bei);
    dinv_k<<<(4 * NND + T - 1) / T, blk>>>();

    part_k<<<4 * NCH, SCB>>>();
    scanpart_k<<<1, 256>>>();
    scan_k<<<4 * NCH, SCB>>>();
    fill_all_k<<<(E_TOT + T - 1) / T, blk>>>(aei, bei);

    const int GEMM_BLOCKS  = (NND + 63) / 64;
    const int NODE_BLOCKS  = (NND * 32 + T - 1) / T;
    const int NODE3_BLOCKS = (3 * NND * 32 + T - 1) / T;

    /* global encoder: 2 layers */
    gemm_k<<<GEMM_BLOCKS, 128>>>(gW, 0);
    gather_k<<<NODE_BLOCKS, blk>>>(gb, 0);
    gemm_k<<<GEMM_BLOCKS, 128>>>(gW + 4096, 1);
    gather_k<<<NODE_BLOCKS, blk>>>(gb + 64, 1);

    /* behavioral encoders */
    dim3 g3(GEMM_BLOCKS, 3);
    gemm3_k<<<g3, 128>>>(bW, 0);
    gather3_k<<<NODE3_BLOCKS, blk>>>(bb);
    gemm3_k<<<g3, 128>>>(bW, 1);
    gather3attn_k<<<NODE_BLOCKS, blk>>>(bb);

    loss_k<<<(BATCH * 9 * 32 + T - 1) / T, blk>>>(bd, out);
    final_k<<<1, 1>>>(out);
}

// round 9
// speedup vs baseline: 1.2414x; 1.1067x over previous
#include <cuda_runtime.h>
#include <cuda_fp16.h>
#include <math.h>
#include <stdint.h>

#define N_USERS 60000
#define N_ITEMS 40000
#define NU      60001
#define NND     100002
#define D       64
#define ND64    (NND * 64)
#define E_GLOBAL 1000000
#define E_BEH    500000
#define E_TOT   (E_GLOBAL + 3 * E_BEH)
#define BATCH    4096

#define SCB 512
#define NCH ((NND + SCB - 1) / SCB)

/* ---------------- scratch ---------------- */
__device__ __align__(16) __half g_hw[ND64];       /* global dinv*h@W (fp16) */
__device__ __align__(16) __half g_hwb[3][ND64];   /* behavioral dinv*h@W (fp16) */
__device__ __align__(16) __half g_b16[ND64];      /* fp16 GEMM input "base" */
__device__ __align__(16) __half g_h16[ND64];      /* fp16 global h */
__device__ __align__(16) __half g_hb16[3][ND64];  /* fp16 behavioral h */
__device__ __align__(16) __half g_beh16[3][ND64]; /* fp16 behavioral res (tok input) */
__device__ float  g_base[ND64];                   /* fp32 global res */
__device__ float  g_w[3][ND64];                   /* combined uw/iw (marked rows only) */
__device__ float  g_dinv[4 * NND];
__device__ int    g_deg[4 * NND];
__device__ int    g_part[4 * NCH];
__device__ int    g_ptr[4 * (NND + 1)];
__device__ int    g_cnt[4 * NND];
__device__ int    g_csr[E_TOT];
__device__ unsigned char g_mark[NND];
__device__ float  g_sc[2];

/* ---------------- helpers ---------------- */
__device__ __forceinline__ float warp_sum(float v) {
#pragma unroll
    for (int o = 16; o; o >>= 1) v += __shfl_xor_sync(0xffffffffu, v, o);
    return v;
}

#define FMA2(d, a, b) asm("fma.rn.f32x2 %0, %1, %2, %0;" : "+l"(d) : "l"(a), "l"(b))
#define PACK2(p, f)   asm("mov.b64 %0, {%1, %1};" : "=l"(p) : "r"(__float_as_uint(f)))

__device__ __forceinline__ uint32_t f2h2(float2 v) {
    __half2 h = __floats2half2_rn(v.x, v.y);
    return *(uint32_t*)&h;
}
__device__ __forceinline__ float2 h22f2(uint32_t u) {
    return __half22float2(*(__half2*)&u);
}

/* ---------------- tiny zero (things concat would race on) ---------------- */
__global__ void zero0_k(float* out) {
    if (threadIdx.x < 2) g_sc[threadIdx.x] = 0.0f;
    if (threadIdx.x == 2) out[0] = 0.0f;
}

/* ------- concat + fused sumsq + fp16 copy + zero g_deg/g_mark ------- */
__global__ void concat_k(const float* __restrict__ ue, const float* __restrict__ ie) {
    int t = blockIdx.x * blockDim.x + threadIdx.x;
    if (t < 4 * NND) g_deg[t] = 0;
    if (t < NND) g_mark[t] = 0;
    float su = 0.0f, si = 0.0f;
    if (t < NND * 16) {
        int node = t >> 4, q = t & 15;
        float4 v;
        if (node < NU) {
            v = ((const float4*)ue)[node * 16 + q];
            su = v.x * v.x + v.y * v.y + v.z * v.z + v.w * v.w;
        } else {
            v = ((const float4*)ie)[(node - NU) * 16 + q];
            si = v.x * v.x + v.y * v.y + v.z * v.z + v.w * v.w;
        }
        ((float4*)g_base)[t] = v;
        uint2 p;
        p.x = f2h2(make_float2(v.x, v.y));
        p.y = f2h2(make_float2(v.z, v.w));
        ((uint2*)g_b16)[t] = p;
    }
    su = warp_sum(su);
    si = warp_sum(si);
    __shared__ float smu[8], smi[8];
    int w = threadIdx.x >> 5, l = threadIdx.x & 31;
    if (l == 0) { smu[w] = su; smi[w] = si; }
    __syncthreads();
    if (threadIdx.x == 0) {
        float a = 0.f, b = 0.f;
#pragma unroll
        for (int q = 0; q < 8; q++) { a += smu[q]; b += smi[q]; }
        if (a != 0.f) atomicAdd(&g_sc[0], a);
        if (b != 0.f) atomicAdd(&g_sc[1], b);
    }
}

/* ---------------- mark nodes needed by the loss ---------------- */
__global__ void mark_k(const int* __restrict__ bd) {
    int t = blockIdx.x * blockDim.x + threadIdx.x;
    if (t >= BATCH * 9) return;
    int k = t / 9, r = t - k * 9;
    int i = r / 3, c = r - i * 3;
    int val = bd[k * 9 + i * 3 + c];
    if (c == 0) g_mark[val] = 1;          /* user row */
    else        g_mark[NU + val] = 1;     /* item row */
}

/* ---------------- degrees for all 4 graphs ---------------- */
__global__ void degcnt_all_k(const int* __restrict__ aei, const int* __restrict__ bei) {
    int i = blockIdx.x * blockDim.x + threadIdx.x;
    if (i >= E_TOT) return;
    int g, d;
    if (i < E_GLOBAL) {
        g = 0;
        d = aei[E_GLOBAL + i];
    } else {
        int r = i - E_GLOBAL;
        int b = r / E_BEH, o = r - b * E_BEH;
        g = 1 + b;
        d = bei[(b * 2 + 1) * E_BEH + o];
    }
    atomicAdd(&g_deg[g * NND + d], 1);
}

__global__ void dinv_k() {
    int i = blockIdx.x * blockDim.x + threadIdx.x;
    if (i < 4 * NND) {
        int d = g_deg[i];
        g_dinv[i] = (d > 0) ? rsqrtf((float)d) : 0.0f;
    }
}

/* ---------------- CSR build ---------------- */
__global__ __launch_bounds__(SCB) void part_k() {
    __shared__ int sm[SCB];
    int b = blockIdx.x;
    int g = b / NCH, ch = b % NCH;
    int idx = ch * SCB + threadIdx.x;
    int v = (idx < NND) ? g_deg[g * NND + idx] : 0;
    sm[threadIdx.x] = v;
    __syncthreads();
    for (int o = SCB / 2; o; o >>= 1) {
        if (threadIdx.x < o) sm[threadIdx.x] += sm[threadIdx.x + o];
        __syncthreads();
    }
    if (threadIdx.x == 0) g_part[b] = sm[0];
}

__global__ __launch_bounds__(256) void scanpart_k() {
    __shared__ int sm[256];
    for (int g = 0; g < 4; g++) {
        int v = (threadIdx.x < NCH) ? g_part[g * NCH + threadIdx.x] : 0;
        sm[threadIdx.x] = v;
        __syncthreads();
        for (int o = 1; o < 256; o <<= 1) {
            int a = (threadIdx.x >= o) ? sm[threadIdx.x - o] : 0;
            __syncthreads();
            sm[threadIdx.x] += a;
            __syncthreads();
        }
        if (threadIdx.x < NCH) g_part[g * NCH + threadIdx.x] = sm[threadIdx.x] - v;
        if (threadIdx.x == NCH - 1) g_ptr[g * (NND + 1) + NND] = sm[threadIdx.x];
        __syncthreads();
    }
}

__global__ __launch_bounds__(SCB) void scan_k() {
    __shared__ int sm[SCB];
    int b = blockIdx.x;
    int g = b / NCH, ch = b % NCH;
    int idx = ch * SCB + threadIdx.x;
    int v = (idx < NND) ? g_deg[g * NND + idx] : 0;
    sm[threadIdx.x] = v;
    __syncthreads();
    for (int o = 1; o < SCB; o <<= 1) {
        int add = (threadIdx.x >= o) ? sm[threadIdx.x - o] : 0;
        __syncthreads();
        sm[threadIdx.x] += add;
        __syncthreads();
    }
    int excl = sm[threadIdx.x] - v + g_part[b];
    if (idx < NND) {
        g_ptr[g * (NND + 1) + idx] = excl;
        g_cnt[g * NND + idx]       = excl;
    }
}

__global__ void fill_all_k(const int* __restrict__ aei, const int* __restrict__ bei) {
    int i = blockIdx.x * blockDim.x + threadIdx.x;
    if (i >= E_TOT) return;
    int g, s, d, base;
    if (i < E_GLOBAL) {
        g = 0;
        s = aei[i];
        d = aei[E_GLOBAL + i];
        base = 0;
    } else {
        int r = i - E_GLOBAL;
        int b = r / E_BEH, o = r - b * E_BEH;
        g = 1 + b;
        s = bei[(b * 2) * E_BEH + o];
        d = bei[(b * 2 + 1) * E_BEH + o];
        base = E_GLOBAL + b * E_BEH;
    }
    int pos = atomicAdd(&g_cnt[g * NND + d], 1);
    g_csr[base + pos] = s;
}

/* --------- GEMM body: HW = fp16(dinv * (A16 @ W)) --------- */
__device__ __forceinline__ void gemm_body(const __half* __restrict__ A16,
                                          const float* __restrict__ W,
                                          __half* __restrict__ HW, int row0,
                                          const float* __restrict__ dv) {
    __shared__ float sA[64 * 65];
    __shared__ float sW[64 * 64];
    int tid = threadIdx.x;

#pragma unroll
    for (int i = tid; i < 1024; i += 128) ((float4*)sW)[i] = ((const float4*)W)[i];
#pragma unroll
    for (int i = tid; i < 1024; i += 128) {
        int r = i >> 4, q = i & 15;
        int row = row0 + r;
        uint2 u = make_uint2(0u, 0u);
        if (row < NND) u = ((const uint2*)A16)[row * 16 + q];
        float2 f0 = h22f2(u.x);
        float2 f1 = h22f2(u.y);
        int base = r * 65 + q * 4;
        sA[base + 0] = f0.x; sA[base + 1] = f0.y;
        sA[base + 2] = f1.x; sA[base + 3] = f1.y;
    }
    __syncthreads();

    int tx = tid & 7, ty = tid >> 3;
    int c0 = tx * 4, c1 = 32 + tx * 4, r0 = ty * 4;

    unsigned long long acc[4][4] = {};
    const unsigned long long* sW64 = (const unsigned long long*)sW;

#pragma unroll 8
    for (int k = 0; k < 64; k++) {
        unsigned long long w0 = sW64[(k * 64 + c0) >> 1];
        unsigned long long w1 = sW64[(k * 64 + c0 + 2) >> 1];
        unsigned long long w2 = sW64[(k * 64 + c1) >> 1];
        unsigned long long w3 = sW64[(k * 64 + c1 + 2) >> 1];
#pragma unroll
        for (int i = 0; i < 4; i++) {
            float a = sA[(r0 + i) * 65 + k];
            unsigned long long a2;
            PACK2(a2, a);
            FMA2(acc[i][0], a2, w0);
            FMA2(acc[i][1], a2, w1);
            FMA2(acc[i][2], a2, w2);
            FMA2(acc[i][3], a2, w3);
        }
    }

#pragma unroll
    for (int i = 0; i < 4; i++) {
        int row = row0 + r0 + i;
        if (row >= NND) break;
        float s = dv[row];
        float2 p0 = *(float2*)&acc[i][0];
        float2 p1 = *(float2*)&acc[i][1];
        float2 p2 = *(float2*)&acc[i][2];
        float2 p3 = *(float2*)&acc[i][3];
        uint2 pa, pb;
        pa.x = f2h2(make_float2(p0.x * s, p0.y * s));
        pa.y = f2h2(make_float2(p1.x * s, p1.y * s));
        pb.x = f2h2(make_float2(p2.x * s, p2.y * s));
        pb.y = f2h2(make_float2(p3.x * s, p3.y * s));
        ((uint2*)HW)[row * 16 + tx]     = pa;
        ((uint2*)HW)[row * 16 + 8 + tx] = pb;
    }
}

__global__ __launch_bounds__(128) void gemm_k(const float* __restrict__ W, int srcsel) {
    gemm_body(srcsel ? g_h16 : g_b16, W, g_hw, blockIdx.x * 64, g_dinv);
}

__global__ __launch_bounds__(128) void gemm3_k(const float* __restrict__ bW, int l) {
    int b = blockIdx.y;
    const __half* A16 = l ? g_hb16[b] : g_b16;
    gemm_body(A16, bW + (b * 2 + l) * 4096, g_hwb[b], blockIdx.x * 64,
              g_dinv + (1 + b) * NND);
}

/* ------- gather core: lane owns cols 2*lane, 2*lane+1; unroll 8 ------- */
__device__ __forceinline__ float2 gather_core(
    const __half* __restrict__ HW, int csr_base, int g,
    const float* __restrict__ bias, int node, int lane) {

    const int* ptr = g_ptr + g * (NND + 1);
    const int* csr = g_csr + csr_base;
    const uint32_t* HW32 = (const uint32_t*)HW;
    int beg = ptr[node], end = ptr[node + 1];

    float2 acc = make_float2(0.f, 0.f);
    int k = beg;
    for (; k + 8 <= end; k += 8) {
        uint32_t u[8];
#pragma unroll
        for (int j = 0; j < 8; j++) u[j] = HW32[csr[k + j] * 32 + lane];
#pragma unroll
        for (int j = 0; j < 8; j++) {
            float2 v = h22f2(u[j]);
            acc.x += v.x;
            acc.y += v.y;
        }
    }
    for (; k + 4 <= end; k += 4) {
        uint32_t u[4];
#pragma unroll
        for (int j = 0; j < 4; j++) u[j] = HW32[csr[k + j] * 32 + lane];
#pragma unroll
        for (int j = 0; j < 4; j++) {
            float2 v = h22f2(u[j]);
            acc.x += v.x;
            acc.y += v.y;
        }
    }
    for (; k < end; k++) {
        float2 v = h22f2(HW32[csr[k] * 32 + lane]);
        acc.x += v.x;
        acc.y += v.y;
    }

    float dd = g_dinv[g * NND + node];
    float2 bv = ((const float2*)bias)[lane];
    float2 o = make_float2(acc.x * dd + bv.x, acc.y * dd + bv.y);
    float ss  = warp_sum(o.x * o.x + o.y * o.y);
    float inv = 1.0f / fmaxf(sqrtf(ss), 1e-12f);
    return make_float2(o.x * inv, o.y * inv);
}

/* global gather. mode 0: base += h, h16 = h.  mode 1: base += h/2, b16 = fp16(base). */
__global__ void gather_k(const float* __restrict__ bias, int mode) {
    int t = blockIdx.x * blockDim.x + threadIdx.x;
    int node = t >> 5, lane = t & 31;
    if (node >= NND) return;
    int off = node * 32 + lane;
    float2 h = gather_core(g_hw, 0, 0, bias, node, lane);
    float2 r = ((const float2*)g_base)[off];
    if (mode == 0) {
        float2 nb = make_float2(r.x + h.x, r.y + h.y);
        ((float2*)g_base)[off] = nb;
        ((uint32_t*)g_h16)[off] = f2h2(h);
    } else {
        float2 nb = make_float2(r.x + 0.5f * h.x, r.y + 0.5f * h.y);
        ((float2*)g_base)[off] = nb;
        ((uint32_t*)g_b16)[off] = f2h2(nb);
    }
}

/* behavioral layer 0 gather (batched): h16 -> g_hb16, res(fp16) -> g_beh16 */
__global__ void gather3_k(const float* __restrict__ bb) {
    int t = blockIdx.x * blockDim.x + threadIdx.x;
    int w = t >> 5, lane = t & 31;
    if (w >= 3 * NND) return;
    int b = w / NND, node = w - b * NND;
    int off = node * 32 + lane;
    float2 h = gather_core(g_hwb[b], E_GLOBAL + b * E_BEH, 1 + b,
                           bb + (b * 2) * 64, node, lane);
    ((uint32_t*)g_hb16[b])[off] = f2h2(h);
    float2 r = ((const float2*)g_base)[off];
    ((uint32_t*)g_beh16[b])[off] = f2h2(make_float2(r.x + h.x, r.y + h.y));
}

/* behavioral layer 1 gather FUSED with attention+combine — MARKED NODES ONLY */
__global__ void gather3attn_k(const float* __restrict__ bb) {
    int t = blockIdx.x * blockDim.x + threadIdx.x;
    int node = t >> 5, lane = t & 31;
    if (node >= NND) return;
    if (!g_mark[node]) return;
    int off = node * 32 + lane;

    float2 tok[3];
#pragma unroll
    for (int b = 0; b < 3; b++) {
        float2 h = gather_core(g_hwb[b], E_GLOBAL + b * E_BEH, 1 + b,
                               bb + (b * 2 + 1) * 64, node, lane);
        float2 r = h22f2(((const uint32_t*)g_beh16[b])[off]);
        tok[b] = make_float2(r.x + 0.5f * h.x, r.y + 0.5f * h.y);
    }

    float s00 = warp_sum(tok[0].x * tok[0].x + tok[0].y * tok[0].y);
    float s01 = warp_sum(tok[0].x * tok[1].x + tok[0].y * tok[1].y);
    float s02 = warp_sum(tok[0].x * tok[2].x + tok[0].y * tok[2].y);
    float s11 = warp_sum(tok[1].x * tok[1].x + tok[1].y * tok[1].y);
    float s12 = warp_sum(tok[1].x * tok[2].x + tok[1].y * tok[2].y);
    float s22 = warp_sum(tok[2].x * tok[2].x + tok[2].y * tok[2].y);

    const float sc = 0.125f;
    float s[3][3] = {{s00 * sc, s01 * sc, s02 * sc},
                     {s01 * sc, s11 * sc, s12 * sc},
                     {s02 * sc, s12 * sc, s22 * sc}};

    bool isU = node < NU;
    float gw = isU ? 2.35f : 1.0f;
    float bw = isU ? 0.242f : 0.55f;
    float2 gv = ((const float2*)g_base)[off];

#pragma unroll
    for (int b = 0; b < 3; b++) {
        float m  = fmaxf(s[b][0], fmaxf(s[b][1], s[b][2]));
        float e0 = __expf(s[b][0] - m), e1 = __expf(s[b][1] - m), e2 = __expf(s[b][2] - m);
        float is = 1.0f / (e0 + e1 + e2);
        float a0 = e0 * is, a1 = e1 * is, a2 = e2 * is;
        float2 o = make_float2(a0 * tok[0].x + a1 * tok[1].x + a2 * tok[2].x,
                               a0 * tok[0].y + a1 * tok[1].y + a2 * tok[2].y);
        ((float2*)g_w[b])[off] = make_float2(gw * gv.x + bw * o.x,
                                             gw * gv.y + bw * o.y);
    }
}

/* ---------------- BPR loss ---------------- */
__global__ void loss_k(const int* __restrict__ bd, float* out) {
    int t = blockIdx.x * blockDim.x + threadIdx.x;
    int w = t >> 5, lane = t & 31;
    float partial = 0.0f;
    if (w < BATCH * 9) {
        int k = w / 9, pr = w - k * 9;
        int i = pr / 3, j = pr - i * 3;
        int u   = bd[k * 9 + i * 3 + 0];
        int ip  = bd[k * 9 + i * 3 + 1];
        int in_ = bd[k * 9 + i * 3 + 2];
        float2 uu = ((const float2*)g_w[i])[u * 32 + lane];
        float2 pp = ((const float2*)g_w[j])[(NU + ip) * 32 + lane];
        float2 nn = ((const float2*)g_w[j])[(NU + in_) * 32 + lane];
        float sp = warp_sum(uu.x * pp.x + uu.y * pp.y);
        float sn = warp_sum(uu.x * nn.x + uu.y * nn.y);
        float x  = sp - sn;
        float ls = fminf(x, 0.0f) - log1pf(expf(-fabsf(x)));
        partial = -ls * (1.0f / (float)BATCH);
    }
    __shared__ float sm[8];
    if (lane == 0) sm[threadIdx.x >> 5] = partial;
    __syncthreads();
    if (threadIdx.x == 0) {
        float s = 0.0f;
#pragma unroll
        for (int q = 0; q < 8; q++) s += sm[q];
        atomicAdd(out, s);
    }
}

__global__ void final_k(float* out) {
    out[0] += 0.001f * ((sqrtf(g_sc[0]) + sqrtf(g_sc[1])) / (float)(N_ITEMS + 1));
}

/* ================================ launch ================================ */
extern "C" void kernel_launch(void* const* d_in, const int* in_sizes, int n_in,
                              void* d_out, int out_size) {
    const float* ue  = (const float*)d_in[0];
    const float* ie  = (const float*)d_in[1];
    const float* gW  = (const float*)d_in[2];
    const float* gb  = (const float*)d_in[3];
    const float* bW  = (const float*)d_in[4];
    const float* bb  = (const float*)d_in[5];
    const int*   aei = (const int*)d_in[6];
    const int*   bei = (const int*)d_in[7];
    const int*   bd  = (const int*)d_in[8];
    float* out = (float*)d_out;

    const int T = 256;
    dim3 blk(T);

    zero0_k<<<1, 32>>>(out);
    concat_k<<<(NND * 16 + T - 1) / T, blk>>>(ue, ie);
    mark_k<<<(BATCH * 9 + T - 1) / T, blk>>>(bd);

    degcnt_all_k<<<(E_TOT + T - 1) / T, blk>>>(aei, bei);
    dinv_k<<<(4 * NND + T - 1) / T, blk>>>();

    part_k<<<4 * NCH, SCB>>>();
    scanpart_k<<<1, 256>>>();
    scan_k<<<4 * NCH, SCB>>>();
    fill_all_k<<<(E_TOT + T - 1) / T, blk>>>(aei, bei);

    const int GEMM_BLOCKS  = (NND + 63) / 64;
    const int NODE_BLOCKS  = (NND * 32 + T - 1) / T;
    const int NODE3_BLOCKS = (3 * NND * 32 + T - 1) / T;

    /* global encoder: 2 layers */
    gemm_k<<<GEMM_BLOCKS, 128>>>(gW, 0);
    gather_k<<<NODE_BLOCKS, blk>>>(gb, 0);
    gemm_k<<<GEMM_BLOCKS, 128>>>(gW + 4096, 1);
    gather_k<<<NODE_BLOCKS, blk>>>(gb + 64, 1);

    /* behavioral encoders */
    dim3 g3(GEMM_BLOCKS, 3);
    gemm3_k<<<g3, 128>>>(bW, 0);
    gather3_k<<<NODE3_BLOCKS, blk>>>(bb);
    gemm3_k<<<g3, 128>>>(bW, 1);
    gather3attn_k<<<NODE_BLOCKS, blk>>>(bb);

    loss_k<<<(BATCH * 9 * 32 + T - 1) / T, blk>>>(bd, out);
    final_k<<<1, 1>>>(out);
}

// round 10
// speedup vs baseline: 1.4937x; 1.2032x over previous
#include <cuda_runtime.h>
#include <cuda_fp16.h>
#include <math.h>
#include <stdint.h>

#define N_USERS 60000
#define N_ITEMS 40000
#define NU      60001
#define NND     100002
#define D       64
#define ND64    (NND * 64)
#define E_GLOBAL 1000000
#define E_BEH    500000
#define E_TOT   (E_GLOBAL + 3 * E_BEH)
#define BATCH    4096

#define SCB 512
#define NCH ((NND + SCB - 1) / SCB)

/* ---------------- scratch ---------------- */
__device__ __align__(16) __half g_hw[ND64];       /* global dinv*h@W (fp16) */
__device__ __align__(16) __half g_hwb[3][ND64];   /* behavioral dinv*h@W (fp16) */
__device__ __align__(16) __half g_b16[ND64];      /* fp16 GEMM input "base" */
__device__ __align__(16) __half g_h16[ND64];      /* fp16 global h */
__device__ __align__(16) __half g_hb16[3][ND64];  /* fp16 behavioral h */
__device__ __align__(16) __half g_beh16[3][ND64]; /* fp16 behavioral res */
__device__ float  g_base[ND64];                   /* fp32 global res */
__device__ float  g_w[3][ND64];                   /* combined uw/iw (marked rows) */
__device__ float  g_dinv[4 * NND];
__device__ int    g_deg[4 * NND];
__device__ int    g_part[4 * NCH];
__device__ int    g_ptr[4 * (NND + 1)];
__device__ int    g_cnt[4 * NND];
__device__ int    g_csr[E_TOT];
__device__ unsigned char g_mark[NND];
__device__ float  g_sc[2];

/* ---------------- helpers ---------------- */
__device__ __forceinline__ float warp_sum(float v) {
#pragma unroll
    for (int o = 16; o; o >>= 1) v += __shfl_xor_sync(0xffffffffu, v, o);
    return v;
}
__device__ __forceinline__ uint32_t f2h2(float2 v) {
    __half2 h = __floats2half2_rn(v.x, v.y);
    return *(uint32_t*)&h;
}
__device__ __forceinline__ float2 h22f2(uint32_t u) {
    return __half22float2(*(__half2*)&u);
}

__device__ __forceinline__ void mma16816(float4& c, uint32_t a0, uint32_t a1,
                                         uint32_t a2, uint32_t a3,
                                         uint32_t b0, uint32_t b1) {
    asm volatile(
        "mma.sync.aligned.m16n8k16.row.col.f32.f16.f16.f32 "
        "{%0,%1,%2,%3}, {%4,%5,%6,%7}, {%8,%9}, {%0,%1,%2,%3};"
        : "+f"(c.x), "+f"(c.y), "+f"(c.z), "+f"(c.w)
        : "r"(a0), "r"(a1), "r"(a2), "r"(a3), "r"(b0), "r"(b1));
}

/* ---------------- tiny zero ---------------- */
__global__ void zero0_k(float* out) {
    if (threadIdx.x < 2) g_sc[threadIdx.x] = 0.0f;
    if (threadIdx.x == 2) out[0] = 0.0f;
}

/* ------- concat + fused sumsq + fp16 copy + zero g_deg/g_mark ------- */
__global__ void concat_k(const float* __restrict__ ue, const float* __restrict__ ie) {
    int t = blockIdx.x * blockDim.x + threadIdx.x;
    if (t < 4 * NND) g_deg[t] = 0;
    if (t < NND) g_mark[t] = 0;
    float su = 0.0f, si = 0.0f;
    if (t < NND * 16) {
        int node = t >> 4, q = t & 15;
        float4 v;
        if (node < NU) {
            v = ((const float4*)ue)[node * 16 + q];
            su = v.x * v.x + v.y * v.y + v.z * v.z + v.w * v.w;
        } else {
            v = ((const float4*)ie)[(node - NU) * 16 + q];
            si = v.x * v.x + v.y * v.y + v.z * v.z + v.w * v.w;
        }
        ((float4*)g_base)[t] = v;
        uint2 p;
        p.x = f2h2(make_float2(v.x, v.y));
        p.y = f2h2(make_float2(v.z, v.w));
        ((uint2*)g_b16)[t] = p;
    }
    su = warp_sum(su);
    si = warp_sum(si);
    __shared__ float smu[8], smi[8];
    int w = threadIdx.x >> 5, l = threadIdx.x & 31;
    if (l == 0) { smu[w] = su; smi[w] = si; }
    __syncthreads();
    if (threadIdx.x == 0) {
        float a = 0.f, b = 0.f;
#pragma unroll
        for (int q = 0; q < 8; q++) { a += smu[q]; b += smi[q]; }
        if (a != 0.f) atomicAdd(&g_sc[0], a);
        if (b != 0.f) atomicAdd(&g_sc[1], b);
    }
}

/* ---------------- mark nodes needed by the loss ---------------- */
__global__ void mark_k(const int* __restrict__ bd) {
    int t = blockIdx.x * blockDim.x + threadIdx.x;
    if (t >= BATCH * 9) return;
    int k = t / 9, r = t - k * 9;
    int i = r / 3, c = r - i * 3;
    int val = bd[k * 9 + i * 3 + c];
    if (c == 0) g_mark[val] = 1;
    else        g_mark[NU + val] = 1;
}

/* ---------------- degrees, 4 edges per thread (int4) ---------------- */
__global__ void degcnt_all_k(const int* __restrict__ aei, const int* __restrict__ bei) {
    int q = blockIdx.x * blockDim.x + threadIdx.x;   /* quad index */
    if (q >= E_TOT / 4) return;
    int4 d4;
    int g;
    if (q < E_GLOBAL / 4) {
        g = 0;
        d4 = ((const int4*)(aei + E_GLOBAL))[q];
    } else {
        int r = q - E_GLOBAL / 4;
        int b = r / (E_BEH / 4), o = r - b * (E_BEH / 4);
        g = 1 + b;
        d4 = ((const int4*)(bei + (b * 2 + 1) * E_BEH))[o];
    }
    int* deg = g_deg + g * NND;
    atomicAdd(&deg[d4.x], 1);
    atomicAdd(&deg[d4.y], 1);
    atomicAdd(&deg[d4.z], 1);
    atomicAdd(&deg[d4.w], 1);
}

__global__ void dinv_k() {
    int i = blockIdx.x * blockDim.x + threadIdx.x;
    if (i < 4 * NND) {
        int d = g_deg[i];
        g_dinv[i] = (d > 0) ? rsqrtf((float)d) : 0.0f;
    }
}

/* ---------------- CSR build ---------------- */
__global__ __launch_bounds__(SCB) void part_k() {
    __shared__ int sm[SCB];
    int b = blockIdx.x;
    int g = b / NCH, ch = b % NCH;
    int idx = ch * SCB + threadIdx.x;
    int v = (idx < NND) ? g_deg[g * NND + idx] : 0;
    sm[threadIdx.x] = v;
    __syncthreads();
    for (int o = SCB / 2; o; o >>= 1) {
        if (threadIdx.x < o) sm[threadIdx.x] += sm[threadIdx.x + o];
        __syncthreads();
    }
    if (threadIdx.x == 0) g_part[b] = sm[0];
}

__global__ __launch_bounds__(256) void scanpart_k() {
    __shared__ int sm[256];
    for (int g = 0; g < 4; g++) {
        int v = (threadIdx.x < NCH) ? g_part[g * NCH + threadIdx.x] : 0;
        sm[threadIdx.x] = v;
        __syncthreads();
        for (int o = 1; o < 256; o <<= 1) {
            int a = (threadIdx.x >= o) ? sm[threadIdx.x - o] : 0;
            __syncthreads();
            sm[threadIdx.x] += a;
            __syncthreads();
        }
        if (threadIdx.x < NCH) g_part[g * NCH + threadIdx.x] = sm[threadIdx.x] - v;
        if (threadIdx.x == NCH - 1) g_ptr[g * (NND + 1) + NND] = sm[threadIdx.x];
        __syncthreads();
    }
}

__global__ __launch_bounds__(SCB) void scan_k() {
    __shared__ int sm[SCB];
    int b = blockIdx.x;
    int g = b / NCH, ch = b % NCH;
    int idx = ch * SCB + threadIdx.x;
    int v = (idx < NND) ? g_deg[g * NND + idx] : 0;
    sm[threadIdx.x] = v;
    __syncthreads();
    for (int o = 1; o < SCB; o <<= 1) {
        int add = (threadIdx.x >= o) ? sm[threadIdx.x - o] : 0;
        __syncthreads();
        sm[threadIdx.x] += add;
        __syncthreads();
    }
    int excl = sm[threadIdx.x] - v + g_part[b];
    if (idx < NND) {
        g_ptr[g * (NND + 1) + idx] = excl;
        g_cnt[g * NND + idx]       = excl;
    }
}

/* ---------------- fill, 4 edges per thread ---------------- */
__global__ void fill_all_k(const int* __restrict__ aei, const int* __restrict__ bei) {
    int q = blockIdx.x * blockDim.x + threadIdx.x;
    if (q >= E_TOT / 4) return;
    int4 s4, d4;
    int g, base;
    if (q < E_GLOBAL / 4) {
        g = 0;
        base = 0;
        s4 = ((const int4*)aei)[q];
        d4 = ((const int4*)(aei + E_GLOBAL))[q];
    } else {
        int r = q - E_GLOBAL / 4;
        int b = r / (E_BEH / 4), o = r - b * (E_BEH / 4);
        g = 1 + b;
        base = E_GLOBAL + b * E_BEH;
        s4 = ((const int4*)(bei + (b * 2) * E_BEH))[o];
        d4 = ((const int4*)(bei + (b * 2 + 1) * E_BEH))[o];
    }
    int* cnt = g_cnt + g * NND;
    int* csr = g_csr + base;
    csr[atomicAdd(&cnt[d4.x], 1)] = s4.x;
    csr[atomicAdd(&cnt[d4.y], 1)] = s4.y;
    csr[atomicAdd(&cnt[d4.z], 1)] = s4.z;
    csr[atomicAdd(&cnt[d4.w], 1)] = s4.w;
}

/* --------- HMMA GEMM: HW = fp16(dinv * (A16 @ W)), 128 rows/CTA --------- */
#define SAS 72   /* smem row stride in halves */
__device__ __forceinline__ void gemm_body(const __half* __restrict__ A16,
                                          const float* __restrict__ W,
                                          __half* __restrict__ HW, int row0,
                                          const float* __restrict__ dv) {
    __shared__ __half sA[128 * SAS];
    __shared__ __half sWt[64 * SAS];   /* transposed: sWt[n][k] */
    int tid = threadIdx.x;

    /* load A tile: 1024 uint4 */
#pragma unroll
    for (int i = 0; i < 4; i++) {
        int idx = tid + i * 256;
        int r = idx >> 3, c8 = idx & 7;
        uint4 u = make_uint4(0u, 0u, 0u, 0u);
        int row = row0 + r;
        if (row < NND) u = ((const uint4*)A16)[row * 8 + c8];
        *(uint4*)(sA + r * SAS + c8 * 8) = u;
    }
    /* load W transposed: read float4 coalesced, scatter halves */
#pragma unroll
    for (int i = 0; i < 4; i++) {
        int idx = tid + i * 256;           /* 1024 float4 */
        int k = idx >> 4, n4 = (idx & 15) * 4;
        float4 w = ((const float4*)W)[idx];
        sWt[(n4 + 0) * SAS + k] = __float2half_rn(w.x);
        sWt[(n4 + 1) * SAS + k] = __float2half_rn(w.y);
        sWt[(n4 + 2) * SAS + k] = __float2half_rn(w.z);
        sWt[(n4 + 3) * SAS + k] = __float2half_rn(w.w);
    }
    __syncthreads();

    int wid = tid >> 5, lane = tid & 31;
    int gq = lane >> 2, tg = lane & 3;       /* group, thread-in-group */
    int mrow = wid * 16;                      /* warp m-tile base (local) */

    float4 acc[8];
#pragma unroll
    for (int n = 0; n < 8; n++) acc[n] = make_float4(0.f, 0.f, 0.f, 0.f);

#pragma unroll
    for (int ks = 0; ks < 4; ks++) {
        int k0 = ks * 16 + tg * 2;
        uint32_t a0 = *(uint32_t*)(sA + (mrow + gq) * SAS + k0);
        uint32_t a1 = *(uint32_t*)(sA + (mrow + gq + 8) * SAS + k0);
        uint32_t a2 = *(uint32_t*)(sA + (mrow + gq) * SAS + k0 + 8);
        uint32_t a3 = *(uint32_t*)(sA + (mrow + gq + 8) * SAS + k0 + 8);
#pragma unroll
        for (int n = 0; n < 8; n++) {
            uint32_t b0 = *(uint32_t*)(sWt + (n * 8 + gq) * SAS + k0);
            uint32_t b1 = *(uint32_t*)(sWt + (n * 8 + gq) * SAS + k0 + 8);
            mma16816(acc[n], a0, a1, a2, a3, b0, b1);
        }
    }

    /* epilogue: rows r0 = row0+mrow+gq, r1 = +8; cols n*8 + 2*tg (+1) */
    int r0 = row0 + mrow + gq;
    int r1 = r0 + 8;
    float s0 = (r0 < NND) ? dv[r0] : 0.0f;
    float s1 = (r1 < NND) ? dv[r1] : 0.0f;
#pragma unroll
    for (int n = 0; n < 8; n++) {
        int col = n * 8 + tg * 2;
        if (r0 < NND)
            *(uint32_t*)(HW + r0 * 64 + col) = f2h2(make_float2(acc[n].x * s0, acc[n].y * s0));
        if (r1 < NND)
            *(uint32_t*)(HW + r1 * 64 + col) = f2h2(make_float2(acc[n].z * s1, acc[n].w * s1));
    }
}

__global__ __launch_bounds__(256) void gemm_k(const float* __restrict__ W, int srcsel) {
    gemm_body(srcsel ? g_h16 : g_b16, W, g_hw, blockIdx.x * 128, g_dinv);
}

__global__ __launch_bounds__(256) void gemm3_k(const float* __restrict__ bW, int l) {
    int b = blockIdx.y;
    const __half* A16 = l ? g_hb16[b] : g_b16;
    gemm_body(A16, bW + (b * 2 + l) * 4096, g_hwb[b], blockIdx.x * 128,
              g_dinv + (1 + b) * NND);
}

/* ------- gather core ------- */
__device__ __forceinline__ float2 gather_core(
    const __half* __restrict__ HW, int csr_base, int g,
    const float* __restrict__ bias, int node, int lane) {

    const int* ptr = g_ptr + g * (NND + 1);
    const int* csr = g_csr + csr_base;
    const uint32_t* HW32 = (const uint32_t*)HW;
    int beg = ptr[node], end = ptr[node + 1];

    float2 acc = make_float2(0.f, 0.f);
    int k = beg;
    for (; k + 8 <= end; k += 8) {
        uint32_t u[8];
#pragma unroll
        for (int j = 0; j < 8; j++) u[j] = HW32[csr[k + j] * 32 + lane];
#pragma unroll
        for (int j = 0; j < 8; j++) {
            float2 v = h22f2(u[j]);
            acc.x += v.x;
            acc.y += v.y;
        }
    }
    for (; k + 4 <= end; k += 4) {
        uint32_t u[4];
#pragma unroll
        for (int j = 0; j < 4; j++) u[j] = HW32[csr[k + j] * 32 + lane];
#pragma unroll
        for (int j = 0; j < 4; j++) {
            float2 v = h22f2(u[j]);
            acc.x += v.x;
            acc.y += v.y;
        }
    }
    for (; k < end; k++) {
        float2 v = h22f2(HW32[csr[k] * 32 + lane]);
        acc.x += v.x;
        acc.y += v.y;
    }

    float dd = g_dinv[g * NND + node];
    float2 bv = ((const float2*)bias)[lane];
    float2 o = make_float2(acc.x * dd + bv.x, acc.y * dd + bv.y);
    float ss  = warp_sum(o.x * o.x + o.y * o.y);
    float inv = 1.0f / fmaxf(sqrtf(ss), 1e-12f);
    return make_float2(o.x * inv, o.y * inv);
}

/* global gather */
__global__ void gather_k(const float* __restrict__ bias, int mode) {
    int t = blockIdx.x * blockDim.x + threadIdx.x;
    int node = t >> 5, lane = t & 31;
    if (node >= NND) return;
    int off = node * 32 + lane;
    float2 h = gather_core(g_hw, 0, 0, bias, node, lane);
    float2 r = ((const float2*)g_base)[off];
    if (mode == 0) {
        float2 nb = make_float2(r.x + h.x, r.y + h.y);
        ((float2*)g_base)[off] = nb;
        ((uint32_t*)g_h16)[off] = f2h2(h);
    } else {
        float2 nb = make_float2(r.x + 0.5f * h.x, r.y + 0.5f * h.y);
        ((float2*)g_base)[off] = nb;
        ((uint32_t*)g_b16)[off] = f2h2(nb);
    }
}

/* behavioral layer 0 gather */
__global__ void gather3_k(const float* __restrict__ bb) {
    int t = blockIdx.x * blockDim.x + threadIdx.x;
    int w = t >> 5, lane = t & 31;
    if (w >= 3 * NND) return;
    int b = w / NND, node = w - b * NND;
    int off = node * 32 + lane;
    float2 h = gather_core(g_hwb[b], E_GLOBAL + b * E_BEH, 1 + b,
                           bb + (b * 2) * 64, node, lane);
    ((uint32_t*)g_hb16[b])[off] = f2h2(h);
    float2 r = ((const float2*)g_base)[off];
    ((uint32_t*)g_beh16[b])[off] = f2h2(make_float2(r.x + h.x, r.y + h.y));
}

/* behavioral layer 1 gather + attention + combine — MARKED NODES ONLY */
__global__ void gather3attn_k(const float* __restrict__ bb) {
    int t = blockIdx.x * blockDim.x + threadIdx.x;
    int node = t >> 5, lane = t & 31;
    if (node >= NND) return;
    if (!g_mark[node]) return;
    int off = node * 32 + lane;

    float2 tok[3];
#pragma unroll
    for (int b = 0; b < 3; b++) {
        float2 h = gather_core(g_hwb[b], E_GLOBAL + b * E_BEH, 1 + b,
                               bb + (b * 2 + 1) * 64, node, lane);
        float2 r = h22f2(((const uint32_t*)g_beh16[b])[off]);
        tok[b] = make_float2(r.x + 0.5f * h.x, r.y + 0.5f * h.y);
    }

    float s00 = warp_sum(tok[0].x * tok[0].x + tok[0].y * tok[0].y);
    float s01 = warp_sum(tok[0].x * tok[1].x + tok[0].y * tok[1].y);
    float s02 = warp_sum(tok[0].x * tok[2].x + tok[0].y * tok[2].y);
    float s11 = warp_sum(tok[1].x * tok[1].x + tok[1].y * tok[1].y);
    float s12 = warp_sum(tok[1].x * tok[2].x + tok[1].y * tok[2].y);
    float s22 = warp_sum(tok[2].x * tok[2].x + tok[2].y * tok[2].y);

    const float sc = 0.125f;
    float s[3][3] = {{s00 * sc, s01 * sc, s02 * sc},
                     {s01 * sc, s11 * sc, s12 * sc},
                     {s02 * sc, s12 * sc, s22 * sc}};

    bool isU = node < NU;
    float gw = isU ? 2.35f : 1.0f;
    float bw = isU ? 0.242f : 0.55f;
    float2 gv = ((const float2*)g_base)[off];

#pragma unroll
    for (int b = 0; b < 3; b++) {
        float m  = fmaxf(s[b][0], fmaxf(s[b][1], s[b][2]));
        float e0 = __expf(s[b][0] - m), e1 = __expf(s[b][1] - m), e2 = __expf(s[b][2] - m);
        float is = 1.0f / (e0 + e1 + e2);
        float a0 = e0 * is, a1 = e1 * is, a2 = e2 * is;
        float2 o = make_float2(a0 * tok[0].x + a1 * tok[1].x + a2 * tok[2].x,
                               a0 * tok[0].y + a1 * tok[1].y + a2 * tok[2].y);
        ((float2*)g_w[b])[off] = make_float2(gw * gv.x + bw * o.x,
                                             gw * gv.y + bw * o.y);
    }
}

/* ---------------- BPR loss ---------------- */
__global__ void loss_k(const int* __restrict__ bd, float* out) {
    int t = blockIdx.x * blockDim.x + threadIdx.x;
    int w = t >> 5, lane = t & 31;
    float partial = 0.0f;
    if (w < BATCH * 9) {
        int k = w / 9, pr = w - k * 9;
        int i = pr / 3, j = pr - i * 3;
        int u   = bd[k * 9 + i * 3 + 0];
        int ip  = bd[k * 9 + i * 3 + 1];
        int in_ = bd[k * 9 + i * 3 + 2];
        float2 uu = ((const float2*)g_w[i])[u * 32 + lane];
        float2 pp = ((const float2*)g_w[j])[(NU + ip) * 32 + lane];
        float2 nn = ((const float2*)g_w[j])[(NU + in_) * 32 + lane];
        float sp = warp_sum(uu.x * pp.x + uu.y * pp.y);
        float sn = warp_sum(uu.x * nn.x + uu.y * nn.y);
        float x  = sp - sn;
        float ls = fminf(x, 0.0f) - log1pf(expf(-fabsf(x)));
        partial = -ls * (1.0f / (float)BATCH);
    }
    __shared__ float sm[8];
    if (lane == 0) sm[threadIdx.x >> 5] = partial;
    __syncthreads();
    if (threadIdx.x == 0) {
        float s = 0.0f;
#pragma unroll
        for (int q = 0; q < 8; q++) s += sm[q];
        atomicAdd(out, s);
    }
}

__global__ void final_k(float* out) {
    out[0] += 0.001f * ((sqrtf(g_sc[0]) + sqrtf(g_sc[1])) / (float)(N_ITEMS + 1));
}

/* ================================ launch ================================ */
extern "C" void kernel_launch(void* const* d_in, const int* in_sizes, int n_in,
                              void* d_out, int out_size) {
    const float* ue  = (const float*)d_in[0];
    const float* ie  = (const float*)d_in[1];
    const float* gW  = (const float*)d_in[2];
    const float* gb  = (const float*)d_in[3];
    const float* bW  = (const float*)d_in[4];
    const float* bb  = (const float*)d_in[5];
    const int*   aei = (const int*)d_in[6];
    const int*   bei = (const int*)d_in[7];
    const int*   bd  = (const int*)d_in[8];
    float* out = (float*)d_out;

    const int T = 256;
    dim3 blk(T);

    zero0_k<<<1, 32>>>(out);
    concat_k<<<(NND * 16 + T - 1) / T, blk>>>(ue, ie);
    mark_k<<<(BATCH * 9 + T - 1) / T, blk>>>(bd);

    degcnt_all_k<<<(E_TOT / 4 + T - 1) / T, blk>>>(aei, bei);
    dinv_k<<<(4 * NND + T - 1) / T, blk>>>();

    part_k<<<4 * NCH, SCB>>>();
    scanpart_k<<<1, 256>>>();
    scan_k<<<4 * NCH, SCB>>>();
    fill_all_k<<<(E_TOT / 4 + T - 1) / T, blk>>>(aei, bei);

    const int GEMM_BLOCKS  = (NND + 127) / 128;
    const int NODE_BLOCKS  = (NND * 32 + T - 1) / T;
    const int NODE3_BLOCKS = (3 * NND * 32 + T - 1) / T;

    /* global encoder: 2 layers */
    gemm_k<<<GEMM_BLOCKS, 256>>>(gW, 0);
    gather_k<<<NODE_BLOCKS, blk>>>(gb, 0);
    gemm_k<<<GEMM_BLOCKS, 256>>>(gW + 4096, 1);
    gather_k<<<NODE_BLOCKS, blk>>>(gb + 64, 1);

    /* behavioral encoders */
    dim3 g3(GEMM_BLOCKS, 3);
    gemm3_k<<<g3, 256>>>(bW, 0);
    gather3_k<<<NODE3_BLOCKS, blk>>>(bb);
    gemm3_k<<<g3, 256>>>(bW, 1);
    gather3attn_k<<<NODE_BLOCKS, blk>>>(bb);

    loss_k<<<(BATCH * 9 * 32 + T - 1) / T, blk>>>(bd, out);
    final_k<<<1, 1>>>(out);
}

// round 11
// speedup vs baseline: 1.7530x; 1.1736x over previous
#include <cuda_runtime.h>
#include <cuda_fp16.h>
#include <math.h>
#include <stdint.h>

#define N_USERS 60000
#define N_ITEMS 40000
#define NU      60001
#define NND     100002
#define NND2    (NND / 2)
#define D       64
#define ND64    (NND * 64)
#define E_GLOBAL 1000000
#define E_BEH    500000
#define E_TOT   (E_GLOBAL + 3 * E_BEH)
#define BATCH    4096

#define SCB 512
#define NCH ((NND + SCB - 1) / SCB)

/* ---------------- scratch ---------------- */
__device__ __align__(16) __half g_hw[ND64];       /* global dinv*h@W (fp16) */
__device__ __align__(16) __half g_hwb[3][ND64];   /* behavioral dinv*h@W (fp16) */
__device__ __align__(16) __half g_b16[ND64];      /* fp16 GEMM input "base" */
__device__ __align__(16) __half g_h16[ND64];      /* fp16 global h */
__device__ __align__(16) __half g_hb16[3][ND64];  /* fp16 behavioral h */
__device__ __align__(16) __half g_beh16[3][ND64]; /* fp16 behavioral res */
__device__ float  g_base[ND64];                   /* fp32 global res */
__device__ float  g_w[3][ND64];                   /* combined uw/iw (marked rows) */
__device__ float  g_dinv[4 * NND];
__device__ int    g_deg[4 * NND];
__device__ int    g_part[4 * NCH];
__device__ int    g_ptr[4 * (NND + 1)];
__device__ int    g_cnt[4 * NND];
__device__ int    g_csr[E_TOT];
__device__ unsigned char g_mark[NND];
__device__ float  g_sc[2];

/* ---------------- helpers ---------------- */
__device__ __forceinline__ float warp_sum(float v) {
#pragma unroll
    for (int o = 16; o; o >>= 1) v += __shfl_xor_sync(0xffffffffu, v, o);
    return v;
}
__device__ __forceinline__ float hsum16(float v) {
#pragma unroll
    for (int o = 8; o; o >>= 1) v += __shfl_xor_sync(0xffffffffu, v, o);
    return v;
}
__device__ __forceinline__ uint32_t f2h2(float2 v) {
    __half2 h = __floats2half2_rn(v.x, v.y);
    return *(uint32_t*)&h;
}
__device__ __forceinline__ float2 h22f2(uint32_t u) {
    return __half22float2(*(__half2*)&u);
}
__device__ __forceinline__ uint2 f4h4(float4 v) {
    return make_uint2(f2h2(make_float2(v.x, v.y)), f2h2(make_float2(v.z, v.w)));
}

__device__ __forceinline__ void mma16816(float4& c, uint32_t a0, uint32_t a1,
                                         uint32_t a2, uint32_t a3,
                                         uint32_t b0, uint32_t b1) {
    asm volatile(
        "mma.sync.aligned.m16n8k16.row.col.f32.f16.f16.f32 "
        "{%0,%1,%2,%3}, {%4,%5,%6,%7}, {%8,%9}, {%0,%1,%2,%3};"
        : "+f"(c.x), "+f"(c.y), "+f"(c.z), "+f"(c.w)
        : "r"(a0), "r"(a1), "r"(a2), "r"(a3), "r"(b0), "r"(b1));
}

/* ---------------- tiny zero ---------------- */
__global__ void zero0_k(float* out) {
    if (threadIdx.x < 2) g_sc[threadIdx.x] = 0.0f;
    if (threadIdx.x == 2) out[0] = 0.0f;
}

/* ------- concat + fused sumsq + fp16 copy + zero g_deg/g_mark ------- */
__global__ void concat_k(const float* __restrict__ ue, const float* __restrict__ ie) {
    int t = blockIdx.x * blockDim.x + threadIdx.x;
    if (t < 4 * NND) g_deg[t] = 0;
    if (t < NND) g_mark[t] = 0;
    float su = 0.0f, si = 0.0f;
    if (t < NND * 16) {
        int node = t >> 4, q = t & 15;
        float4 v;
        if (node < NU) {
            v = ((const float4*)ue)[node * 16 + q];
            su = v.x * v.x + v.y * v.y + v.z * v.z + v.w * v.w;
        } else {
            v = ((const float4*)ie)[(node - NU) * 16 + q];
            si = v.x * v.x + v.y * v.y + v.z * v.z + v.w * v.w;
        }
        ((float4*)g_base)[t] = v;
        ((uint2*)g_b16)[t] = f4h4(v);
    }
    su = warp_sum(su);
    si = warp_sum(si);
    __shared__ float smu[8], smi[8];
    int w = threadIdx.x >> 5, l = threadIdx.x & 31;
    if (l == 0) { smu[w] = su; smi[w] = si; }
    __syncthreads();
    if (threadIdx.x == 0) {
        float a = 0.f, b = 0.f;
#pragma unroll
        for (int q = 0; q < 8; q++) { a += smu[q]; b += smi[q]; }
        if (a != 0.f) atomicAdd(&g_sc[0], a);
        if (b != 0.f) atomicAdd(&g_sc[1], b);
    }
}

/* ---------------- mark nodes needed by the loss ---------------- */
__global__ void mark_k(const int* __restrict__ bd) {
    int t = blockIdx.x * blockDim.x + threadIdx.x;
    if (t >= BATCH * 9) return;
    int k = t / 9, r = t - k * 9;
    int i = r / 3, c = r - i * 3;
    int val = bd[k * 9 + i * 3 + c];
    if (c == 0) g_mark[val] = 1;
    else        g_mark[NU + val] = 1;
}

/* ---------------- degrees, 4 edges per thread (int4) ---------------- */
__global__ void degcnt_all_k(const int* __restrict__ aei, const int* __restrict__ bei) {
    int q = blockIdx.x * blockDim.x + threadIdx.x;
    if (q >= E_TOT / 4) return;
    int4 d4;
    int g;
    if (q < E_GLOBAL / 4) {
        g = 0;
        d4 = ((const int4*)(aei + E_GLOBAL))[q];
    } else {
        int r = q - E_GLOBAL / 4;
        int b = r / (E_BEH / 4), o = r - b * (E_BEH / 4);
        g = 1 + b;
        d4 = ((const int4*)(bei + (b * 2 + 1) * E_BEH))[o];
    }
    int* deg = g_deg + g * NND;
    atomicAdd(&deg[d4.x], 1);
    atomicAdd(&deg[d4.y], 1);
    atomicAdd(&deg[d4.z], 1);
    atomicAdd(&deg[d4.w], 1);
}

/* ---------------- CSR build ---------------- */
__global__ __launch_bounds__(SCB) void part_k() {
    __shared__ int sm[SCB];
    int b = blockIdx.x;
    int g = b / NCH, ch = b % NCH;
    int idx = ch * SCB + threadIdx.x;
    int v = (idx < NND) ? g_deg[g * NND + idx] : 0;
    sm[threadIdx.x] = v;
    __syncthreads();
    for (int o = SCB / 2; o; o >>= 1) {
        if (threadIdx.x < o) sm[threadIdx.x] += sm[threadIdx.x + o];
        __syncthreads();
    }
    if (threadIdx.x == 0) g_part[b] = sm[0];
}

__global__ __launch_bounds__(256) void scanpart_k() {
    __shared__ int sm[256];
    for (int g = 0; g < 4; g++) {
        int v = (threadIdx.x < NCH) ? g_part[g * NCH + threadIdx.x] : 0;
        sm[threadIdx.x] = v;
        __syncthreads();
        for (int o = 1; o < 256; o <<= 1) {
            int a = (threadIdx.x >= o) ? sm[threadIdx.x - o] : 0;
            __syncthreads();
            sm[threadIdx.x] += a;
            __syncthreads();
        }
        if (threadIdx.x < NCH) g_part[g * NCH + threadIdx.x] = sm[threadIdx.x] - v;
        if (threadIdx.x == NCH - 1) g_ptr[g * (NND + 1) + NND] = sm[threadIdx.x];
        __syncthreads();
    }
}

/* scan + fused dinv */
__global__ __launch_bounds__(SCB) void scan_k() {
    __shared__ int sm[SCB];
    int b = blockIdx.x;
    int g = b / NCH, ch = b % NCH;
    int idx = ch * SCB + threadIdx.x;
    int v = (idx < NND) ? g_deg[g * NND + idx] : 0;
    sm[threadIdx.x] = v;
    __syncthreads();
    for (int o = 1; o < SCB; o <<= 1) {
        int add = (threadIdx.x >= o) ? sm[threadIdx.x - o] : 0;
        __syncthreads();
        sm[threadIdx.x] += add;
        __syncthreads();
    }
    int excl = sm[threadIdx.x] - v + g_part[b];
    if (idx < NND) {
        g_ptr[g * (NND + 1) + idx] = excl;
        g_cnt[g * NND + idx]       = excl;
        g_dinv[g * NND + idx]      = (v > 0) ? rsqrtf((float)v) : 0.0f;
    }
}

/* ---------------- fill, 4 edges per thread ---------------- */
__global__ void fill_all_k(const int* __restrict__ aei, const int* __restrict__ bei) {
    int q = blockIdx.x * blockDim.x + threadIdx.x;
    if (q >= E_TOT / 4) return;
    int4 s4, d4;
    int g, base;
    if (q < E_GLOBAL / 4) {
        g = 0;
        base = 0;
        s4 = ((const int4*)aei)[q];
        d4 = ((const int4*)(aei + E_GLOBAL))[q];
    } else {
        int r = q - E_GLOBAL / 4;
        int b = r / (E_BEH / 4), o = r - b * (E_BEH / 4);
        g = 1 + b;
        base = E_GLOBAL + b * E_BEH;
        s4 = ((const int4*)(bei + (b * 2) * E_BEH))[o];
        d4 = ((const int4*)(bei + (b * 2 + 1) * E_BEH))[o];
    }
    int* cnt = g_cnt + g * NND;
    int* csr = g_csr + base;
    csr[atomicAdd(&cnt[d4.x], 1)] = s4.x;
    csr[atomicAdd(&cnt[d4.y], 1)] = s4.y;
    csr[atomicAdd(&cnt[d4.z], 1)] = s4.z;
    csr[atomicAdd(&cnt[d4.w], 1)] = s4.w;
}

/* --------- HMMA GEMM: HW = fp16(dinv * (A16 @ W)), 128 rows/CTA --------- */
#define SAS 72
__device__ __forceinline__ void gemm_body(const __half* __restrict__ A16,
                                          const float* __restrict__ W,
                                          __half* __restrict__ HW, int row0,
                                          const float* __restrict__ dv) {
    __shared__ __half sA[128 * SAS];
    __shared__ __half sWt[64 * SAS];
    int tid = threadIdx.x;

#pragma unroll
    for (int i = 0; i < 4; i++) {
        int idx = tid + i * 256;
        int r = idx >> 3, c8 = idx & 7;
        uint4 u = make_uint4(0u, 0u, 0u, 0u);
        int row = row0 + r;
        if (row < NND) u = ((const uint4*)A16)[row * 8 + c8];
        *(uint4*)(sA + r * SAS + c8 * 8) = u;
    }
#pragma unroll
    for (int i = 0; i < 4; i++) {
        int idx = tid + i * 256;
        int k = idx >> 4, n4 = (idx & 15) * 4;
        float4 w = ((const float4*)W)[idx];
        sWt[(n4 + 0) * SAS + k] = __float2half_rn(w.x);
        sWt[(n4 + 1) * SAS + k] = __float2half_rn(w.y);
        sWt[(n4 + 2) * SAS + k] = __float2half_rn(w.z);
        sWt[(n4 + 3) * SAS + k] = __float2half_rn(w.w);
    }
    __syncthreads();

    int wid = tid >> 5, lane = tid & 31;
    int gq = lane >> 2, tg = lane & 3;
    int mrow = wid * 16;

    float4 acc[8];
#pragma unroll
    for (int n = 0; n < 8; n++) acc[n] = make_float4(0.f, 0.f, 0.f, 0.f);

#pragma unroll
    for (int ks = 0; ks < 4; ks++) {
        int k0 = ks * 16 + tg * 2;
        uint32_t a0 = *(uint32_t*)(sA + (mrow + gq) * SAS + k0);
        uint32_t a1 = *(uint32_t*)(sA + (mrow + gq + 8) * SAS + k0);
        uint32_t a2 = *(uint32_t*)(sA + (mrow + gq) * SAS + k0 + 8);
        uint32_t a3 = *(uint32_t*)(sA + (mrow + gq + 8) * SAS + k0 + 8);
#pragma unroll
        for (int n = 0; n < 8; n++) {
            uint32_t b0 = *(uint32_t*)(sWt + (n * 8 + gq) * SAS + k0);
            uint32_t b1 = *(uint32_t*)(sWt + (n * 8 + gq) * SAS + k0 + 8);
            mma16816(acc[n], a0, a1, a2, a3, b0, b1);
        }
    }

    int r0 = row0 + mrow + gq;
    int r1 = r0 + 8;
    float s0 = (r0 < NND) ? dv[r0] : 0.0f;
    float s1 = (r1 < NND) ? dv[r1] : 0.0f;
#pragma unroll
    for (int n = 0; n < 8; n++) {
        int col = n * 8 + tg * 2;
        if (r0 < NND)
            *(uint32_t*)(HW + r0 * 64 + col) = f2h2(make_float2(acc[n].x * s0, acc[n].y * s0));
        if (r1 < NND)
            *(uint32_t*)(HW + r1 * 64 + col) = f2h2(make_float2(acc[n].z * s1, acc[n].w * s1));
    }
}

__global__ __launch_bounds__(256) void gemm_k(const float* __restrict__ W, int srcsel) {
    gemm_body(srcsel ? g_h16 : g_b16, W, g_hw, blockIdx.x * 128, g_dinv);
}

__global__ __launch_bounds__(256) void gemm3_k(const float* __restrict__ bW, int l) {
    int b = blockIdx.y;
    const __half* A16 = l ? g_hb16[b] : g_b16;
    gemm_body(A16, bW + (b * 2 + l) * 4096, g_hwb[b], blockIdx.x * 128,
              g_dinv + (1 + b) * NND);
}

/* ------- 16-lane gather core: half-warp per node, lane owns 4 cols ------- */
__device__ __forceinline__ float4 gather_core16(
    const __half* __restrict__ HW, int csr_base, int g,
    const float* __restrict__ bias, int node, int sub, bool active) {

    const int* ptr = g_ptr + g * (NND + 1);
    const int* csr = g_csr + csr_base;
    const uint2* HW64 = (const uint2*)HW;   /* 16 uint2 per 64-half row */
    int beg = 0, end = 0;
    if (active) { beg = ptr[node]; end = ptr[node + 1]; }

    float4 acc = make_float4(0.f, 0.f, 0.f, 0.f);
    int k = beg;
    for (; k + 8 <= end; k += 8) {
        uint2 u[8];
#pragma unroll
        for (int j = 0; j < 8; j++) u[j] = HW64[csr[k + j] * 16 + sub];
#pragma unroll
        for (int j = 0; j < 8; j++) {
            float2 a = h22f2(u[j].x), b = h22f2(u[j].y);
            acc.x += a.x; acc.y += a.y; acc.z += b.x; acc.w += b.y;
        }
    }
    for (; k + 4 <= end; k += 4) {
        uint2 u[4];
#pragma unroll
        for (int j = 0; j < 4; j++) u[j] = HW64[csr[k + j] * 16 + sub];
#pragma unroll
        for (int j = 0; j < 4; j++) {
            float2 a = h22f2(u[j].x), b = h22f2(u[j].y);
            acc.x += a.x; acc.y += a.y; acc.z += b.x; acc.w += b.y;
        }
    }
    for (; k < end; k++) {
        uint2 u = HW64[csr[k] * 16 + sub];
        float2 a = h22f2(u.x), b = h22f2(u.y);
        acc.x += a.x; acc.y += a.y; acc.z += b.x; acc.w += b.y;
    }

    float dd = active ? g_dinv[g * NND + node] : 0.0f;
    float4 bv = ((const float4*)bias)[sub];
    float4 o = make_float4(acc.x * dd + bv.x, acc.y * dd + bv.y,
                           acc.z * dd + bv.z, acc.w * dd + bv.w);
    float ss = hsum16(o.x * o.x + o.y * o.y + o.z * o.z + o.w * o.w);
    float inv = 1.0f / fmaxf(sqrtf(ss), 1e-12f);
    return make_float4(o.x * inv, o.y * inv, o.z * inv, o.w * inv);
}

/* global gather: 2 nodes per warp */
__global__ void gather_k(const float* __restrict__ bias, int mode) {
    int t = blockIdx.x * blockDim.x + threadIdx.x;
    int w = t >> 5, lane = t & 31;
    if (w >= NND2) return;
    int sub = lane & 15;
    int node = w * 2 + (lane >> 4);
    int off = node * 16 + sub;

    float4 h = gather_core16(g_hw, 0, 0, bias, node, sub, true);
    float4 r = ((const float4*)g_base)[off];
    if (mode == 0) {
        float4 nb = make_float4(r.x + h.x, r.y + h.y, r.z + h.z, r.w + h.w);
        ((float4*)g_base)[off] = nb;
        ((uint2*)g_h16)[off] = f4h4(h);
    } else {
        float4 nb = make_float4(r.x + 0.5f * h.x, r.y + 0.5f * h.y,
                                r.z + 0.5f * h.z, r.w + 0.5f * h.w);
        ((float4*)g_base)[off] = nb;
        ((uint2*)g_b16)[off] = f4h4(nb);
    }
}

/* behavioral layer 0 gather: 2 nodes per warp, 3 behaviors */
__global__ void gather3_k(const float* __restrict__ bb) {
    int t = blockIdx.x * blockDim.x + threadIdx.x;
    int w = t >> 5, lane = t & 31;
    if (w >= 3 * NND2) return;
    int b = w / NND2, i = w - b * NND2;
    int sub = lane & 15;
    int node = i * 2 + (lane >> 4);
    int off = node * 16 + sub;

    float4 h = gather_core16(g_hwb[b], E_GLOBAL + b * E_BEH, 1 + b,
                             bb + (b * 2) * 64, node, sub, true);
    ((uint2*)g_hb16[b])[off] = f4h4(h);
    float4 r = ((const float4*)g_base)[off];
    ((uint2*)g_beh16[b])[off] =
        f4h4(make_float4(r.x + h.x, r.y + h.y, r.z + h.z, r.w + h.w));
}

/* behavioral layer 1 gather + attention + combine — marked nodes, 2/warp */
__global__ void gather3attn_k(const float* __restrict__ bb) {
    int t = blockIdx.x * blockDim.x + threadIdx.x;
    int w = t >> 5, lane = t & 31;
    if (w >= NND2) return;
    int sub = lane & 15;
    int node = w * 2 + (lane >> 4);
    bool act = g_mark[node] != 0;
    if (__ballot_sync(0xffffffffu, act) == 0u) return;   /* whole warp idle */
    int off = node * 16 + sub;

    float4 tok[3];
#pragma unroll
    for (int b = 0; b < 3; b++) {
        float4 h = gather_core16(g_hwb[b], E_GLOBAL + b * E_BEH, 1 + b,
                                 bb + (b * 2 + 1) * 64, node, sub, act);
        float4 r = make_float4(0.f, 0.f, 0.f, 0.f);
        if (act) {
            uint2 u = ((const uint2*)g_beh16[b])[off];
            float2 a = h22f2(u.x), c = h22f2(u.y);
            r = make_float4(a.x, a.y, c.x, c.y);
        }
        tok[b] = make_float4(r.x + 0.5f * h.x, r.y + 0.5f * h.y,
                             r.z + 0.5f * h.z, r.w + 0.5f * h.w);
    }

#define DOT4(p, q) (p.x * q.x + p.y * q.y + p.z * q.z + p.w * q.w)
    float s00 = hsum16(DOT4(tok[0], tok[0]));
    float s01 = hsum16(DOT4(tok[0], tok[1]));
    float s02 = hsum16(DOT4(tok[0], tok[2]));
    float s11 = hsum16(DOT4(tok[1], tok[1]));
    float s12 = hsum16(DOT4(tok[1], tok[2]));
    float s22 = hsum16(DOT4(tok[2], tok[2]));
#undef DOT4

    const float sc = 0.125f;
    float s[3][3] = {{s00 * sc, s01 * sc, s02 * sc},
                     {s01 * sc, s11 * sc, s12 * sc},
                     {s02 * sc, s12 * sc, s22 * sc}};

    if (!act) return;

    bool isU = node < NU;
    float gw = isU ? 2.35f : 1.0f;
    float bw = isU ? 0.242f : 0.55f;
    float4 gv = ((const float4*)g_base)[off];

#pragma unroll
    for (int b = 0; b < 3; b++) {
        float m  = fmaxf(s[b][0], fmaxf(s[b][1], s[b][2]));
        float e0 = __expf(s[b][0] - m), e1 = __expf(s[b][1] - m), e2 = __expf(s[b][2] - m);
        float is = 1.0f / (e0 + e1 + e2);
        float a0 = e0 * is, a1 = e1 * is, a2 = e2 * is;
        float4 o = make_float4(
            a0 * tok[0].x + a1 * tok[1].x + a2 * tok[2].x,
            a0 * tok[0].y + a1 * tok[1].y + a2 * tok[2].y,
            a0 * tok[0].z + a1 * tok[1].z + a2 * tok[2].z,
            a0 * tok[0].w + a1 * tok[1].w + a2 * tok[2].w);
        ((float4*)g_w[b])[off] = make_float4(gw * gv.x + bw * o.x,
                                             gw * gv.y + bw * o.y,
                                             gw * gv.z + bw * o.z,
                                             gw * gv.w + bw * o.w);
    }
}

/* ---------------- BPR loss ---------------- */
__global__ void loss_k(const int* __restrict__ bd, float* out) {
    int t = blockIdx.x * blockDim.x + threadIdx.x;
    int w = t >> 5, lane = t & 31;
    float partial = 0.0f;
    if (w < BATCH * 9) {
        int k = w / 9, pr = w - k * 9;
        int i = pr / 3, j = pr - i * 3;
        int u   = bd[k * 9 + i * 3 + 0];
        int ip  = bd[k * 9 + i * 3 + 1];
        int in_ = bd[k * 9 + i * 3 + 2];
        float2 uu = ((const float2*)g_w[i])[u * 32 + lane];
        float2 pp = ((const float2*)g_w[j])[(NU + ip) * 32 + lane];
        float2 nn = ((const float2*)g_w[j])[(NU + in_) * 32 + lane];
        float sp = warp_sum(uu.x * pp.x + uu.y * pp.y);
        float sn = warp_sum(uu.x * nn.x + uu.y * nn.y);
        float x  = sp - sn;
        float ls = fminf(x, 0.0f) - log1pf(expf(-fabsf(x)));
        partial = -ls * (1.0f / (float)BATCH);
    }
    __shared__ float sm[8];
    if (lane == 0) sm[threadIdx.x >> 5] = partial;
    __syncthreads();
    if (threadIdx.x == 0) {
        float s = 0.0f;
#pragma unroll
        for (int q = 0; q < 8; q++) s += sm[q];
        atomicAdd(out, s);
    }
}

__global__ void final_k(float* out) {
    out[0] += 0.001f * ((sqrtf(g_sc[0]) + sqrtf(g_sc[1])) / (float)(N_ITEMS + 1));
}

/* ================================ launch ================================ */
extern "C" void kernel_launch(void* const* d_in, const int* in_sizes, int n_in,
                              void* d_out, int out_size) {
    const float* ue  = (const float*)d_in[0];
    const float* ie  = (const float*)d_in[1];
    const float* gW  = (const float*)d_in[2];
    const float* gb  = (const float*)d_in[3];
    const float* bW  = (const float*)d_in[4];
    const float* bb  = (const float*)d_in[5];
    const int*   aei = (const int*)d_in[6];
    const int*   bei = (const int*)d_in[7];
    const int*   bd  = (const int*)d_in[8];
    float* out = (float*)d_out;

    const int T = 256;
    dim3 blk(T);

    zero0_k<<<1, 32>>>(out);
    concat_k<<<(NND * 16 + T - 1) / T, blk>>>(ue, ie);
    mark_k<<<(BATCH * 9 + T - 1) / T, blk>>>(bd);

    degcnt_all_k<<<(E_TOT / 4 + T - 1) / T, blk>>>(aei, bei);

    part_k<<<4 * NCH, SCB>>>();
    scanpart_k<<<1, 256>>>();
    scan_k<<<4 * NCH, SCB>>>();
    fill_all_k<<<(E_TOT / 4 + T - 1) / T, blk>>>(aei, bei);

    const int GEMM_BLOCKS = (NND + 127) / 128;
    const int GW_BLOCKS   = (NND2 * 32 + T - 1) / T;       /* 2 nodes/warp */
    const int GW3_BLOCKS  = (3 * NND2 * 32 + T - 1) / T;

    /* global encoder: 2 layers */
    gemm_k<<<GEMM_BLOCKS, 256>>>(gW, 0);
    gather_k<<<GW_BLOCKS, blk>>>(gb, 0);
    gemm_k<<<GEMM_BLOCKS, 256>>>(gW + 4096, 1);
    gather_k<<<GW_BLOCKS, blk>>>(gb + 64, 1);

    /* behavioral encoders */
    dim3 g3(GEMM_BLOCKS, 3);
    gemm3_k<<<g3, 256>>>(bW, 0);
    gather3_k<<<GW3_BLOCKS, blk>>>(bb);
    gemm3_k<<<g3, 256>>>(bW, 1);
    gather3attn_k<<<GW_BLOCKS, blk>>>(bb);

    loss_k<<<(BATCH * 9 * 32 + T - 1) / T, blk>>>(bd, out);
    final_k<<<1, 1>>>(out);
}